// round 4
// baseline (speedup 1.0000x reference)
#include <cuda_runtime.h>
#include <cstdint>

#define FULLMASK 0xffffffffu
namespace {
constexpr int B_ = 16, N_ = 4096, S_ = 1024, K_ = 32;
constexpr float EPSF = 1e-5f;
constexpr int FPS_SMEM = 3 * N_ * 4;                       // 49152
constexpr int KNN_SMEM = 4 * N_ * 4;                       // 65536
constexpr int L0_SMEM = (128 * 68 + 67 * 64 + 2048) * 4;   // 60160
constexpr int L1_SMEM = (128 * 68 + 64 * 64 + 2048) * 4;   // 59392
constexpr int L2_SMEM = (64 * 68 + 64 * 128 + 2048) * 4;   // 58368
}

// ------------- scratch: __device__ globals (allocation-free) -------------
__device__ int   g_fps[B_ * S_];
__device__ float g_newxyz[B_ * S_ * 3];
__device__ float g_d2[B_ * N_];
__device__ int   g_nn[B_ * S_ * K_];
__device__ float g_y0[B_ * S_ * K_ * 64];
__device__ float g_y1[B_ * S_ * K_ * 64];
__device__ float g_y2[(size_t)B_ * S_ * K_ * 128];
__device__ float g_part0[4096 * 128];
__device__ float g_part1[4096 * 128];
__device__ float g_part2[8192 * 256];
__device__ float g_scale0[64], g_shift0[64];
__device__ float g_scale1[64], g_shift1[64];
__device__ float g_scale2[128], g_shift2[128];

// ------------- helpers -------------
__device__ __forceinline__ void cmpswap(float& k, int& v, int j, bool dirAsc, int lane) {
    float ok = __shfl_xor_sync(FULLMASK, k, j);
    int   ov = __shfl_xor_sync(FULLMASK, v, j);
    bool takeOther = (((lane & j) == 0) == dirAsc) ? (ok < k) : (ok > k);
    if (takeOther) { k = ok; v = ov; }
}
__device__ __forceinline__ void bitonic_merge_asc(float& k, int& v, int lane) {
    #pragma unroll
    for (int j = 16; j > 0; j >>= 1) cmpswap(k, v, j, true, lane);
}
__device__ __forceinline__ void bitonic_sort_asc(float& k, int& v, int lane) {
    #pragma unroll
    for (int kk = 2; kk <= 16; kk <<= 1) {
        bool dir = ((lane & kk) == 0);
        #pragma unroll
        for (int j = kk >> 1; j > 0; j >>= 1) cmpswap(k, v, j, dir, lane);
    }
    bitonic_merge_asc(k, v, lane);
}

// ------------- FPS: one CTA per batch -------------
__global__ void __launch_bounds__(1024) fps_kernel(const float* __restrict__ xyz) {
    int b = blockIdx.x;
    extern __shared__ float sh[];
    float* sx = sh; float* sy = sh + N_; float* sz = sh + 2 * N_;
    __shared__ float swv[2][32];
    __shared__ int   swi[2][32];
    int t = threadIdx.x, w = t >> 5, lane = t & 31;
    const float* X = xyz + (size_t)b * N_ * 3;
    for (int i = t; i < N_; i += 1024) { sx[i] = X[3*i]; sy[i] = X[3*i+1]; sz[i] = X[3*i+2]; }
    float dist[4];
    #pragma unroll
    for (int r = 0; r < 4; r++) dist[r] = 1e10f;
    int far = 0;
    __syncthreads();
    for (int it = 0; it < S_; ++it) {
        if (t == 0) g_fps[b * S_ + it] = far;
        float cx = sx[far], cy = sy[far], cz = sz[far];
        float bv = -1.0f; int bi = 0;
        #pragma unroll
        for (int r = 0; r < 4; r++) {
            int i = t + r * 1024;
            float dx = __fadd_rn(sx[i], -cx), dy = __fadd_rn(sy[i], -cy), dz = __fadd_rn(sz[i], -cz);
            float d = __fadd_rn(__fadd_rn(__fmul_rn(dx,dx), __fmul_rn(dy,dy)), __fmul_rn(dz,dz));
            float dm = fminf(dist[r], d);
            dist[r] = dm;
            if (dm > bv) { bv = dm; bi = i; }
        }
        #pragma unroll
        for (int off = 16; off; off >>= 1) {
            float ov = __shfl_down_sync(FULLMASK, bv, off);
            int   oi = __shfl_down_sync(FULLMASK, bi, off);
            if (ov > bv || (ov == bv && oi < bi)) { bv = ov; bi = oi; }
        }
        int buf = it & 1;
        if (lane == 0) { swv[buf][w] = bv; swi[buf][w] = bi; }
        __syncthreads();
        float v = swv[buf][lane]; int i2 = swi[buf][lane];
        #pragma unroll
        for (int off = 16; off; off >>= 1) {
            float ov = __shfl_down_sync(FULLMASK, v, off);
            int   oi = __shfl_down_sync(FULLMASK, i2, off);
            if (ov > v || (ov == v && oi < i2)) { v = ov; i2 = oi; }
        }
        far = __shfl_sync(FULLMASK, i2, 0);
    }
}

// ------------- prep: ||x||^2 + gather new_xyz -------------
__global__ void prep_kernel(const float* __restrict__ xyz, float* __restrict__ out, int write_xyz) {
    int i = blockIdx.x * 256 + threadIdx.x;
    if (i < B_ * N_) {
        float x = xyz[3*i], y = xyz[3*i+1], z = xyz[3*i+2];
        g_d2[i] = __fadd_rn(__fadd_rn(__fmul_rn(x,x), __fmul_rn(y,y)), __fmul_rn(z,z));
    }
    if (i < B_ * S_) {
        int b = i >> 10, n = g_fps[i];
        const float* p = xyz + ((size_t)b * N_ + n) * 3;
        float px = p[0], py = p[1], pz = p[2];
        g_newxyz[3*i] = px; g_newxyz[3*i+1] = py; g_newxyz[3*i+2] = pz;
        if (write_xyz) { out[3*i] = px; out[3*i+1] = py; out[3*i+2] = pz; }
    }
}

// ------------- KNN: warp per query, bitonic top-32, exact fp32 -------------
__global__ void __launch_bounds__(256) knn_kernel(const float* __restrict__ xyz) {
    extern __shared__ float sh[];
    float* sx = sh; float* sy = sh + N_; float* sz = sh + 2*N_; float* sd = sh + 3*N_;
    int t = threadIdx.x;
    int b = blockIdx.x >> 7;
    int s0 = (blockIdx.x & 127) * 8;
    const float* X = xyz + (size_t)b * N_ * 3;
    for (int i = t; i < N_; i += 256) {
        sx[i] = X[3*i]; sy[i] = X[3*i+1]; sz[i] = X[3*i+2];
        sd[i] = g_d2[b * N_ + i];
    }
    __syncthreads();
    int w = t >> 5, lane = t & 31;
    int q = b * S_ + s0 + w;
    float qx = g_newxyz[3*q], qy = g_newxyz[3*q+1], qz = g_newxyz[3*q+2];
    float q2 = __fadd_rn(__fadd_rn(__fmul_rn(qx,qx), __fmul_rn(qy,qy)), __fmul_rn(qz,qz));
    float key = 3.0e38f; int kid = 0; float curmax = 3.0e38f;
    for (int c = 0; c < N_ / 32; c++) {
        int p = c * 32 + lane;
        float dot = __fadd_rn(__fadd_rn(__fmul_rn(qx, sx[p]),
                                        __fmul_rn(qy, sy[p])),
                              __fmul_rn(qz, sz[p]));
        float d = __fsub_rn(__fadd_rn(q2, sd[p]), __fmul_rn(2.0f, dot));
        if (!__ballot_sync(FULLMASK, d < curmax)) continue;
        float nk = d; int ni = p;
        bitonic_sort_asc(nk, ni, lane);
        float rk = __shfl_sync(FULLMASK, nk, 31 - lane);
        int   ri = __shfl_sync(FULLMASK, ni, 31 - lane);
        if (rk < key) { key = rk; kid = ri; }
        bitonic_merge_asc(key, kid, lane);
        curmax = __shfl_sync(FULLMASK, key, 31);
    }
    g_nn[q * K_ + lane] = kid;
}

// ------------- layer 0: gather(67ch) + GEMM 67->64 + BN partials -------------
__global__ void __launch_bounds__(256) layer0_kernel(const float* __restrict__ xyz,
                                                     const float* __restrict__ points,
                                                     const float* __restrict__ w,
                                                     const float* __restrict__ bias) {
    extern __shared__ float sh[];
    float* Xs = sh;                  // 128 x 68 : ch 0..63 = points, 64..66 = xyz diff
    float* Ws = Xs + 128 * 68;       // 67 x 64
    float* Red = Ws + 67 * 64;       // 2048
    int t = threadIdx.x;
    for (int idx = t; idx < 67 * 64; idx += 256) {
        int cc = idx >> 6, o = idx & 63;
        int c = (cc < 64) ? (cc + 3) : (cc - 64);
        Ws[idx] = w[o * 67 + c];
    }
    {
        int r = t >> 1, half = t & 1;
        int gr = blockIdx.x * 128 + r;
        int q = gr >> 5, b = gr >> 15;
        int n = g_nn[gr];
        const float4* prow = (const float4*)(points + ((size_t)b * N_ + n) * 64) + half * 8;
        float4* dst = (float4*)(Xs + r * 68) + half * 8;
        #pragma unroll
        for (int qq = 0; qq < 8; qq++) dst[qq] = prow[qq];
        if (half == 0) {
            const float* pp = xyz + ((size_t)b * N_ + n) * 3;
            Xs[r*68+64] = __fadd_rn(pp[0], -g_newxyz[3*q]);
            Xs[r*68+65] = __fadd_rn(pp[1], -g_newxyz[3*q+1]);
            Xs[r*68+66] = __fadd_rn(pp[2], -g_newxyz[3*q+2]);
        }
    }
    __syncthreads();
    int rg = t >> 3, cg = t & 7;
    float acc[4][8];
    #pragma unroll
    for (int i = 0; i < 8; i++) {
        float bb = bias[cg*8+i];
        acc[0][i]=bb; acc[1][i]=bb; acc[2][i]=bb; acc[3][i]=bb;
    }
    const float* xr = Xs + rg * 4 * 68;
    for (int c = 0; c < 67; c++) {
        float a0 = xr[c], a1 = xr[68+c], a2 = xr[136+c], a3 = xr[204+c];
        const float* wr = Ws + c * 64 + cg * 8;
        #pragma unroll
        for (int i = 0; i < 8; i++) {
            float wv = wr[i];
            acc[0][i] = fmaf(a0,wv,acc[0][i]); acc[1][i] = fmaf(a1,wv,acc[1][i]);
            acc[2][i] = fmaf(a2,wv,acc[2][i]); acc[3][i] = fmaf(a3,wv,acc[3][i]);
        }
    }
    size_t base = ((size_t)blockIdx.x * 128 + rg * 4) * 64 + cg * 8;
    #pragma unroll
    for (int r = 0; r < 4; r++) {
        float4* dst = (float4*)(g_y0 + base + r * 64);
        dst[0] = make_float4(acc[r][0],acc[r][1],acc[r][2],acc[r][3]);
        dst[1] = make_float4(acc[r][4],acc[r][5],acc[r][6],acc[r][7]);
    }
    float s1[8], s2[8];
    #pragma unroll
    for (int i = 0; i < 8; i++) {
        s1[i] = acc[0][i]+acc[1][i]+acc[2][i]+acc[3][i];
        s2[i] = acc[0][i]*acc[0][i]+acc[1][i]*acc[1][i]+acc[2][i]*acc[2][i]+acc[3][i]*acc[3][i];
    }
    #pragma unroll
    for (int i = 0; i < 8; i++) Red[rg*64 + cg*8 + i] = s1[i];
    __syncthreads();
    if (t < 64) { float s = 0.f; for (int j = 0; j < 32; j++) s += Red[j*64+t]; g_part0[blockIdx.x*128 + t] = s; }
    __syncthreads();
    #pragma unroll
    for (int i = 0; i < 8; i++) Red[rg*64 + cg*8 + i] = s2[i];
    __syncthreads();
    if (t < 64) { float s = 0.f; for (int j = 0; j < 32; j++) s += Red[j*64+t]; g_part0[blockIdx.x*128 + 64 + t] = s; }
}

// ------------- layer 1: BN0+ReLU fused load, GEMM 64->64 -------------
__global__ void __launch_bounds__(256) layer1_kernel(const float* __restrict__ w,
                                                     const float* __restrict__ bias) {
    extern __shared__ float sh[];
    float* Xs = sh;                  // 128 x 68
    float* Ws = Xs + 128 * 68;       // 64 x 64
    float* Red = Ws + 4096;          // 2048
    __shared__ float sS[64], sH[64];
    int t = threadIdx.x;
    for (int i = t; i < 64; i += 256) { sS[i] = g_scale0[i]; sH[i] = g_shift0[i]; }
    for (int idx = t; idx < 64 * 64; idx += 256) {
        int c = idx >> 6, o = idx & 63;
        Ws[idx] = w[o * 64 + c];
    }
    __syncthreads();
    {
        int r = t >> 1, half = t & 1;
        size_t gr = (size_t)blockIdx.x * 128 + r;
        const float4* src = (const float4*)(g_y0 + gr * 64) + half * 8;
        float4* dst = (float4*)(Xs + r * 68) + half * 8;
        #pragma unroll
        for (int qq = 0; qq < 8; qq++) {
            float4 v = src[qq]; int c0 = half * 32 + qq * 4;
            v.x = fmaxf(0.f, fmaf(v.x, sS[c0],   sH[c0]));
            v.y = fmaxf(0.f, fmaf(v.y, sS[c0+1], sH[c0+1]));
            v.z = fmaxf(0.f, fmaf(v.z, sS[c0+2], sH[c0+2]));
            v.w = fmaxf(0.f, fmaf(v.w, sS[c0+3], sH[c0+3]));
            dst[qq] = v;
        }
    }
    __syncthreads();
    int rg = t >> 3, cg = t & 7;
    float acc[4][8];
    #pragma unroll
    for (int i = 0; i < 8; i++) {
        float bb = bias[cg*8+i];
        acc[0][i]=bb; acc[1][i]=bb; acc[2][i]=bb; acc[3][i]=bb;
    }
    const float* xr = Xs + rg * 4 * 68;
    for (int c = 0; c < 64; c++) {
        float a0 = xr[c], a1 = xr[68+c], a2 = xr[136+c], a3 = xr[204+c];
        const float* wr = Ws + c * 64 + cg * 8;
        #pragma unroll
        for (int i = 0; i < 8; i++) {
            float wv = wr[i];
            acc[0][i] = fmaf(a0,wv,acc[0][i]); acc[1][i] = fmaf(a1,wv,acc[1][i]);
            acc[2][i] = fmaf(a2,wv,acc[2][i]); acc[3][i] = fmaf(a3,wv,acc[3][i]);
        }
    }
    size_t base = ((size_t)blockIdx.x * 128 + rg * 4) * 64 + cg * 8;
    #pragma unroll
    for (int r = 0; r < 4; r++) {
        float4* dst = (float4*)(g_y1 + base + r * 64);
        dst[0] = make_float4(acc[r][0],acc[r][1],acc[r][2],acc[r][3]);
        dst[1] = make_float4(acc[r][4],acc[r][5],acc[r][6],acc[r][7]);
    }
    float s1[8], s2[8];
    #pragma unroll
    for (int i = 0; i < 8; i++) {
        s1[i] = acc[0][i]+acc[1][i]+acc[2][i]+acc[3][i];
        s2[i] = acc[0][i]*acc[0][i]+acc[1][i]*acc[1][i]+acc[2][i]*acc[2][i]+acc[3][i]*acc[3][i];
    }
    #pragma unroll
    for (int i = 0; i < 8; i++) Red[rg*64 + cg*8 + i] = s1[i];
    __syncthreads();
    if (t < 64) { float s = 0.f; for (int j = 0; j < 32; j++) s += Red[j*64+t]; g_part1[blockIdx.x*128 + t] = s; }
    __syncthreads();
    #pragma unroll
    for (int i = 0; i < 8; i++) Red[rg*64 + cg*8 + i] = s2[i];
    __syncthreads();
    if (t < 64) { float s = 0.f; for (int j = 0; j < 32; j++) s += Red[j*64+t]; g_part1[blockIdx.x*128 + 64 + t] = s; }
}

// ------------- layer 2: BN1+ReLU fused load, GEMM 64->128 -------------
__global__ void __launch_bounds__(256) layer2_kernel(const float* __restrict__ w,
                                                     const float* __restrict__ bias) {
    extern __shared__ float sh[];
    float* Xs = sh;                  // 64 x 68
    float* Ws = Xs + 64 * 68;        // 64 x 128
    float* Red = Ws + 8192;          // 2048
    __shared__ float sS[64], sH[64];
    int t = threadIdx.x;
    for (int i = t; i < 64; i += 256) { sS[i] = g_scale1[i]; sH[i] = g_shift1[i]; }
    for (int idx = t; idx < 64 * 128; idx += 256) {
        int c = idx >> 7, o = idx & 127;
        Ws[idx] = w[o * 64 + c];
    }
    __syncthreads();
    {
        int r = t >> 2, quarter = t & 3;
        size_t gr = (size_t)blockIdx.x * 64 + r;
        const float4* src = (const float4*)(g_y1 + gr * 64) + quarter * 4;
        float4* dst = (float4*)(Xs + r * 68) + quarter * 4;
        #pragma unroll
        for (int qq = 0; qq < 4; qq++) {
            float4 v = src[qq]; int c0 = quarter * 16 + qq * 4;
            v.x = fmaxf(0.f, fmaf(v.x, sS[c0],   sH[c0]));
            v.y = fmaxf(0.f, fmaf(v.y, sS[c0+1], sH[c0+1]));
            v.z = fmaxf(0.f, fmaf(v.z, sS[c0+2], sH[c0+2]));
            v.w = fmaxf(0.f, fmaf(v.w, sS[c0+3], sH[c0+3]));
            dst[qq] = v;
        }
    }
    __syncthreads();
    int rg = t >> 3, cg = t & 7;
    float acc[2][16];
    #pragma unroll
    for (int i = 0; i < 16; i++) { float bb = bias[cg*16+i]; acc[0][i]=bb; acc[1][i]=bb; }
    const float* xr = Xs + rg * 2 * 68;
    for (int c = 0; c < 64; c++) {
        float a0 = xr[c], a1 = xr[68+c];
        const float* wr = Ws + c * 128 + cg * 16;
        #pragma unroll
        for (int i = 0; i < 16; i++) {
            float wv = wr[i];
            acc[0][i] = fmaf(a0,wv,acc[0][i]); acc[1][i] = fmaf(a1,wv,acc[1][i]);
        }
    }
    size_t base = ((size_t)blockIdx.x * 64 + rg * 2) * 128 + cg * 16;
    #pragma unroll
    for (int r = 0; r < 2; r++) {
        float4* dst = (float4*)(g_y2 + base + (size_t)r * 128);
        #pragma unroll
        for (int qq = 0; qq < 4; qq++)
            dst[qq] = make_float4(acc[r][qq*4],acc[r][qq*4+1],acc[r][qq*4+2],acc[r][qq*4+3]);
    }
    float s1[16], s2[16];
    #pragma unroll
    for (int i = 0; i < 16; i++) {
        s1[i] = acc[0][i]+acc[1][i];
        s2[i] = acc[0][i]*acc[0][i]+acc[1][i]*acc[1][i];
    }
    #pragma unroll
    for (int p = 0; p < 2; p++) {
        __syncthreads();
        #pragma unroll
        for (int j = 0; j < 8; j++) Red[rg*64 + cg*8 + j] = s1[p*8+j];
        __syncthreads();
        if (t < 64) {
            float s = 0.f; for (int r2 = 0; r2 < 32; r2++) s += Red[r2*64+t];
            int col = (t>>3)*16 + p*8 + (t&7);
            g_part2[blockIdx.x*256 + col] = s;
        }
        __syncthreads();
        #pragma unroll
        for (int j = 0; j < 8; j++) Red[rg*64 + cg*8 + j] = s2[p*8+j];
        __syncthreads();
        if (t < 64) {
            float s = 0.f; for (int r2 = 0; r2 < 32; r2++) s += Red[r2*64+t];
            int col = (t>>3)*16 + p*8 + (t&7);
            g_part2[blockIdx.x*256 + 128 + col] = s;
        }
    }
}

// ------------- BN stats: one block per channel, parallel reduce -------------
__global__ void __launch_bounds__(256) stats_kernel(int layer, int nblk, int C,
                             const float* __restrict__ gamma, const float* __restrict__ beta) {
    int c = blockIdx.x;
    int t = threadIdx.x;
    const float* part = (layer == 0) ? g_part0 : (layer == 1) ? g_part1 : g_part2;
    float s1 = 0.f, s2 = 0.f;
    for (int bk = t; bk < nblk; bk += 256) {
        s1 += part[(size_t)bk*2*C + c];
        s2 += part[(size_t)bk*2*C + C + c];
    }
    __shared__ float r1[256], r2[256];
    r1[t] = s1; r2[t] = s2;
    __syncthreads();
    for (int off = 128; off >= 1; off >>= 1) {
        if (t < off) { r1[t] += r1[t+off]; r2[t] += r2[t+off]; }
        __syncthreads();
    }
    if (t == 0) {
        const float n = 524288.f;
        float mean = r1[0] / n;
        float var = r2[0] / n - mean * mean;
        float sc = gamma[c] * rsqrtf(var + EPSF);
        float sf = beta[c] - mean * sc;
        if (layer == 0)      { g_scale0[c] = sc; g_shift0[c] = sf; }
        else if (layer == 1) { g_scale1[c] = sc; g_shift1[c] = sf; }
        else                 { g_scale2[c] = sc; g_shift2[c] = sf; }
    }
}

// ------------- pool: BN2+ReLU fused max over K, transposed write -------------
__global__ void pool_kernel(float* __restrict__ out, int pts_off) {
    int bs = blockIdx.x;        // b*1024 + s
    int c = threadIdx.x;        // 0..127
    float sc = g_scale2[c], sf = g_shift2[c];
    const float* base = g_y2 + (size_t)bs * K_ * 128 + c;
    float m = -3.4e38f;
    #pragma unroll 4
    for (int k = 0; k < K_; k++) m = fmaxf(m, fmaf(base[(size_t)k * 128], sc, sf));
    m = fmaxf(m, 0.f);
    out[pts_off + (bs >> 10) * (128 * 1024) + c * 1024 + (bs & 1023)] = m;
}

extern "C" void kernel_launch(void* const* d_in, const int* in_sizes, int n_in,
                              void* d_out, int out_size) {
    const float* xyz    = (const float*)d_in[0];
    const float* points = (const float*)d_in[1];
    const float* w0 = (const float*)d_in[2];  const float* b0  = (const float*)d_in[3];
    const float* g0 = (const float*)d_in[4];  const float* be0 = (const float*)d_in[5];
    const float* w1 = (const float*)d_in[6];  const float* b1  = (const float*)d_in[7];
    const float* g1 = (const float*)d_in[8];  const float* be1 = (const float*)d_in[9];
    const float* w2 = (const float*)d_in[10]; const float* b2  = (const float*)d_in[11];
    const float* g2 = (const float*)d_in[12]; const float* be2 = (const float*)d_in[13];
    float* out = (float*)d_out;

    int npts = B_ * 128 * S_;
    int pts_off = out_size - npts;
    if (pts_off < 0) pts_off = 0;

    cudaFuncSetAttribute(fps_kernel,    cudaFuncAttributeMaxDynamicSharedMemorySize, FPS_SMEM);
    cudaFuncSetAttribute(knn_kernel,    cudaFuncAttributeMaxDynamicSharedMemorySize, KNN_SMEM);
    cudaFuncSetAttribute(layer0_kernel, cudaFuncAttributeMaxDynamicSharedMemorySize, L0_SMEM);
    cudaFuncSetAttribute(layer1_kernel, cudaFuncAttributeMaxDynamicSharedMemorySize, L1_SMEM);
    cudaFuncSetAttribute(layer2_kernel, cudaFuncAttributeMaxDynamicSharedMemorySize, L2_SMEM);

    fps_kernel<<<B_, 1024, FPS_SMEM>>>(xyz);
    prep_kernel<<<(B_ * N_ + 255) / 256, 256>>>(xyz, out, pts_off > 0 ? 1 : 0);
    knn_kernel<<<B_ * 128, 256, KNN_SMEM>>>(xyz);
    layer0_kernel<<<4096, 256, L0_SMEM>>>(xyz, points, w0, b0);
    stats_kernel<<<64, 256>>>(0, 4096, 64, g0, be0);
    layer1_kernel<<<4096, 256, L1_SMEM>>>(w1, b1);
    stats_kernel<<<64, 256>>>(1, 4096, 64, g1, be1);
    layer2_kernel<<<8192, 256, L2_SMEM>>>(w2, b2);
    stats_kernel<<<128, 256>>>(2, 8192, 128, g2, be2);
    pool_kernel<<<B_ * S_, 128>>>(out, pts_off);
}

// round 5
// speedup vs baseline: 1.5429x; 1.5429x over previous
#include <cuda_runtime.h>
#include <cstdint>

#define FULLMASK 0xffffffffu
namespace {
constexpr int B_ = 16, N_ = 4096, S_ = 1024, K_ = 32;
constexpr float EPSF = 1e-5f;
constexpr int FPS_SMEM = 3 * N_ * 4;                         // 49152
constexpr int KNN_SMEM = 4 * N_ * 4;                         // 65536
constexpr int L0_SMEM = (68 * 128 + 67 * 64 + 4160) * 4;     // XsT + Ws + Red
constexpr int L1_SMEM = (64 * 128 + 64 * 64 + 4160) * 4;
constexpr int L2_SMEM = (64 * 64 + 64 * 128 + 4256) * 4;
}

// ------------- scratch -------------
__device__ int      g_fps[B_ * S_];
__device__ float    g_newxyz[B_ * S_ * 3];
__device__ float    g_d2[B_ * N_];
__device__ int      g_nn[B_ * S_ * K_];
__device__ float    g_y0[B_ * S_ * K_ * 64];
__device__ float    g_y1[B_ * S_ * K_ * 64];
__device__ float    g_pmax[B_ * S_ * 128];
__device__ float    g_pmin[B_ * S_ * 128];
__device__ float    g_part0[4096 * 128];
__device__ float    g_part1[4096 * 128];
__device__ float    g_part2[8192 * 256];
__device__ float    g_scale0[64], g_shift0[64];
__device__ float    g_scale1[64], g_shift1[64];
__device__ float    g_scale2[128], g_shift2[128];

// ------------- KNN helpers (unchanged, they work) -------------
__device__ __forceinline__ void cmpswap(float& k, int& v, int j, bool dirAsc, int lane) {
    float ok = __shfl_xor_sync(FULLMASK, k, j);
    int   ov = __shfl_xor_sync(FULLMASK, v, j);
    bool takeOther = (((lane & j) == 0) == dirAsc) ? (ok < k) : (ok > k);
    if (takeOther) { k = ok; v = ov; }
}
__device__ __forceinline__ void bitonic_merge_asc(float& k, int& v, int lane) {
    #pragma unroll
    for (int j = 16; j > 0; j >>= 1) cmpswap(k, v, j, true, lane);
}
__device__ __forceinline__ void bitonic_sort_asc(float& k, int& v, int lane) {
    #pragma unroll
    for (int kk = 2; kk <= 16; kk <<= 1) {
        bool dir = ((lane & kk) == 0);
        #pragma unroll
        for (int j = kk >> 1; j > 0; j >>= 1) cmpswap(k, v, j, dir, lane);
    }
    bitonic_merge_asc(k, v, lane);
}

// ------------- FPS: one CTA per batch, REDUX reductions -------------
__global__ void __launch_bounds__(1024) fps_kernel(const float* __restrict__ xyz) {
    int b = blockIdx.x;
    extern __shared__ float sh[];
    float* sx = sh; float* sy = sh + N_; float* sz = sh + 2 * N_;
    __shared__ unsigned swv[2][32];
    __shared__ unsigned swi[2][32];
    int t = threadIdx.x, w = t >> 5, lane = t & 31;
    const float* X = xyz + (size_t)b * N_ * 3;
    for (int i = t; i < N_; i += 1024) { sx[i] = X[3*i]; sy[i] = X[3*i+1]; sz[i] = X[3*i+2]; }
    float dist[4];
    #pragma unroll
    for (int r = 0; r < 4; r++) dist[r] = 1e10f;
    int far = 0;
    __syncthreads();
    for (int it = 0; it < S_; ++it) {
        if (t == 0) g_fps[b * S_ + it] = far;
        float cx = sx[far], cy = sy[far], cz = sz[far];
        float bv = -1.0f; int bi = 0;
        #pragma unroll
        for (int r = 0; r < 4; r++) {
            int i = t + r * 1024;
            float dx = __fadd_rn(sx[i], -cx), dy = __fadd_rn(sy[i], -cy), dz = __fadd_rn(sz[i], -cz);
            float d = __fadd_rn(__fadd_rn(__fmul_rn(dx,dx), __fmul_rn(dy,dy)), __fmul_rn(dz,dz));
            float dm = fminf(dist[r], d);
            dist[r] = dm;
            if (dm > bv) { bv = dm; bi = i; }   // strict > keeps lowest index in-thread
        }
        // warp argmax: max value, then min index among ties (== argmax-first)
        unsigned db = __float_as_uint(bv);      // bv >= 0 after 4 updates
        unsigned mx = __reduce_max_sync(FULLMASK, db);
        unsigned cand = (db == mx) ? (unsigned)bi : 0xffffffffu;
        unsigned mi = __reduce_min_sync(FULLMASK, cand);
        int buf = it & 1;
        if (lane == 0) { swv[buf][w] = mx; swi[buf][w] = mi; }
        __syncthreads();
        unsigned v2 = swv[buf][lane];
        unsigned i2 = swi[buf][lane];
        unsigned mx2 = __reduce_max_sync(FULLMASK, v2);
        unsigned c2 = (v2 == mx2) ? i2 : 0xffffffffu;
        far = (int)__reduce_min_sync(FULLMASK, c2);
    }
}

// ------------- prep: ||x||^2 + gather new_xyz -------------
__global__ void prep_kernel(const float* __restrict__ xyz, float* __restrict__ out, int write_xyz) {
    int i = blockIdx.x * 256 + threadIdx.x;
    if (i < B_ * N_) {
        float x = xyz[3*i], y = xyz[3*i+1], z = xyz[3*i+2];
        g_d2[i] = __fadd_rn(__fadd_rn(__fmul_rn(x,x), __fmul_rn(y,y)), __fmul_rn(z,z));
    }
    if (i < B_ * S_) {
        int b = i >> 10, n = g_fps[i];
        const float* p = xyz + ((size_t)b * N_ + n) * 3;
        float px = p[0], py = p[1], pz = p[2];
        g_newxyz[3*i] = px; g_newxyz[3*i+1] = py; g_newxyz[3*i+2] = pz;
        if (write_xyz) { out[3*i] = px; out[3*i+1] = py; out[3*i+2] = pz; }
    }
}

// ------------- KNN: warp per query, bitonic top-32, exact fp32 -------------
__global__ void __launch_bounds__(256) knn_kernel(const float* __restrict__ xyz) {
    extern __shared__ float sh[];
    float* sx = sh; float* sy = sh + N_; float* sz = sh + 2*N_; float* sd = sh + 3*N_;
    int t = threadIdx.x;
    int b = blockIdx.x >> 7;
    int s0 = (blockIdx.x & 127) * 8;
    const float* X = xyz + (size_t)b * N_ * 3;
    for (int i = t; i < N_; i += 256) {
        sx[i] = X[3*i]; sy[i] = X[3*i+1]; sz[i] = X[3*i+2];
        sd[i] = g_d2[b * N_ + i];
    }
    __syncthreads();
    int w = t >> 5, lane = t & 31;
    int q = b * S_ + s0 + w;
    float qx = g_newxyz[3*q], qy = g_newxyz[3*q+1], qz = g_newxyz[3*q+2];
    float q2 = __fadd_rn(__fadd_rn(__fmul_rn(qx,qx), __fmul_rn(qy,qy)), __fmul_rn(qz,qz));
    float key = 3.0e38f; int kid = 0; float curmax = 3.0e38f;
    for (int c = 0; c < N_ / 32; c++) {
        int p = c * 32 + lane;
        float dot = __fadd_rn(__fadd_rn(__fmul_rn(qx, sx[p]),
                                        __fmul_rn(qy, sy[p])),
                              __fmul_rn(qz, sz[p]));
        float d = __fsub_rn(__fadd_rn(q2, sd[p]), __fmul_rn(2.0f, dot));
        if (!__ballot_sync(FULLMASK, d < curmax)) continue;
        float nk = d; int ni = p;
        bitonic_sort_asc(nk, ni, lane);
        float rk = __shfl_sync(FULLMASK, nk, 31 - lane);
        int   ri = __shfl_sync(FULLMASK, ni, 31 - lane);
        if (rk < key) { key = rk; kid = ri; }
        bitonic_merge_asc(key, kid, lane);
        curmax = __shfl_sync(FULLMASK, key, 31);
    }
    g_nn[q * K_ + lane] = kid;
}

// ------------- layer 0: gather + GEMM 67->64 (channel-major tile) -------------
__global__ void __launch_bounds__(256) layer0_kernel(const float* __restrict__ xyz,
                                                     const float* __restrict__ points,
                                                     const float* __restrict__ w,
                                                     const float* __restrict__ bias) {
    extern __shared__ float sh[];
    float* XsT = sh;                   // [68][128] channel-major
    float* Ws  = XsT + 68 * 128;       // [67][64]
    float* Red = Ws + 67 * 64;         // 4160: s1 @ rg*65+col, s2 @ 2080+...
    int t = threadIdx.x;
    for (int idx = t; idx < 67 * 64; idx += 256) {
        int cc = idx >> 6, o = idx & 63;
        int c = (cc < 64) ? (cc + 3) : (cc - 64);    // points-first channel order
        Ws[idx] = w[o * 67 + c];
    }
    {
        int r = t & 127, half = t >> 7;
        int gr = blockIdx.x * 128 + r;
        int q = gr >> 5, b = gr >> 15;
        int n = g_nn[gr];
        const float4* prow = (const float4*)(points + ((size_t)b * N_ + n) * 64);
        for (int ch = half; ch < 16; ch += 2) {
            float4 v = prow[ch];
            XsT[(ch*4+0)*128 + r] = v.x;
            XsT[(ch*4+1)*128 + r] = v.y;
            XsT[(ch*4+2)*128 + r] = v.z;
            XsT[(ch*4+3)*128 + r] = v.w;
        }
        if (half == 0) {
            const float* pp = xyz + ((size_t)b * N_ + n) * 3;
            XsT[64*128 + r] = __fadd_rn(pp[0], -g_newxyz[3*q]);
            XsT[65*128 + r] = __fadd_rn(pp[1], -g_newxyz[3*q+1]);
            XsT[66*128 + r] = __fadd_rn(pp[2], -g_newxyz[3*q+2]);
        }
    }
    __syncthreads();
    int rg = t >> 3, cg = t & 7;       // rows rg*4..+3, cols cg*8..+7
    float acc[4][8];
    #pragma unroll
    for (int i = 0; i < 8; i++) {
        float bb = bias[cg*8+i];
        acc[0][i]=bb; acc[1][i]=bb; acc[2][i]=bb; acc[3][i]=bb;
    }
    for (int c = 0; c < 67; c++) {
        float4 a = *(const float4*)(XsT + c*128 + rg*4);
        const float4* wp = (const float4*)(Ws + c*64 + cg*8);
        float4 w0 = wp[0], w1 = wp[1];
        float av[4] = {a.x, a.y, a.z, a.w};
        float wv[8] = {w0.x,w0.y,w0.z,w0.w,w1.x,w1.y,w1.z,w1.w};
        #pragma unroll
        for (int r = 0; r < 4; r++)
            #pragma unroll
            for (int i = 0; i < 8; i++)
                acc[r][i] = fmaf(av[r], wv[i], acc[r][i]);
    }
    size_t base = ((size_t)blockIdx.x * 128 + rg * 4) * 64 + cg * 8;
    #pragma unroll
    for (int r = 0; r < 4; r++) {
        float4* dst = (float4*)(g_y0 + base + r * 64);
        dst[0] = make_float4(acc[r][0],acc[r][1],acc[r][2],acc[r][3]);
        dst[1] = make_float4(acc[r][4],acc[r][5],acc[r][6],acc[r][7]);
    }
    #pragma unroll
    for (int i = 0; i < 8; i++) {
        int col = cg*8 + i;
        Red[rg*65 + col]        = acc[0][i]+acc[1][i]+acc[2][i]+acc[3][i];
        Red[2080 + rg*65 + col] = acc[0][i]*acc[0][i]+acc[1][i]*acc[1][i]
                                 +acc[2][i]*acc[2][i]+acc[3][i]*acc[3][i];
    }
    __syncthreads();
    if (t < 64) {
        float s = 0.f;
        for (int j = 0; j < 32; j++) s += Red[j*65 + t];
        g_part0[blockIdx.x*128 + t] = s;
    } else if (t < 128) {
        int col = t - 64; float s = 0.f;
        for (int j = 0; j < 32; j++) s += Red[2080 + j*65 + col];
        g_part0[blockIdx.x*128 + 64 + col] = s;
    }
}

// ------------- layer 1: BN0+ReLU fused gather, GEMM 64->64 -------------
__global__ void __launch_bounds__(256) layer1_kernel(const float* __restrict__ w,
                                                     const float* __restrict__ bias) {
    extern __shared__ float sh[];
    float* XsT = sh;                   // [64][128]
    float* Ws  = XsT + 64 * 128;       // [64][64]
    float* Red = Ws + 64 * 64;         // 4160
    __shared__ float sS[64], sH[64];
    int t = threadIdx.x;
    if (t < 64) { sS[t] = g_scale0[t]; sH[t] = g_shift0[t]; }
    for (int idx = t; idx < 64 * 64; idx += 256) {
        int c = idx >> 6, o = idx & 63;
        Ws[idx] = w[o * 64 + c];
    }
    __syncthreads();
    {
        int r = t & 127, half = t >> 7;
        size_t gr = (size_t)blockIdx.x * 128 + r;
        const float4* src = (const float4*)(g_y0 + gr * 64);
        for (int ch = half; ch < 16; ch += 2) {
            float4 v = src[ch]; int c0 = ch * 4;
            XsT[(c0+0)*128 + r] = fmaxf(0.f, fmaf(v.x, sS[c0],   sH[c0]));
            XsT[(c0+1)*128 + r] = fmaxf(0.f, fmaf(v.y, sS[c0+1], sH[c0+1]));
            XsT[(c0+2)*128 + r] = fmaxf(0.f, fmaf(v.z, sS[c0+2], sH[c0+2]));
            XsT[(c0+3)*128 + r] = fmaxf(0.f, fmaf(v.w, sS[c0+3], sH[c0+3]));
        }
    }
    __syncthreads();
    int rg = t >> 3, cg = t & 7;
    float acc[4][8];
    #pragma unroll
    for (int i = 0; i < 8; i++) {
        float bb = bias[cg*8+i];
        acc[0][i]=bb; acc[1][i]=bb; acc[2][i]=bb; acc[3][i]=bb;
    }
    for (int c = 0; c < 64; c++) {
        float4 a = *(const float4*)(XsT + c*128 + rg*4);
        const float4* wp = (const float4*)(Ws + c*64 + cg*8);
        float4 w0 = wp[0], w1 = wp[1];
        float av[4] = {a.x, a.y, a.z, a.w};
        float wv[8] = {w0.x,w0.y,w0.z,w0.w,w1.x,w1.y,w1.z,w1.w};
        #pragma unroll
        for (int r = 0; r < 4; r++)
            #pragma unroll
            for (int i = 0; i < 8; i++)
                acc[r][i] = fmaf(av[r], wv[i], acc[r][i]);
    }
    size_t base = ((size_t)blockIdx.x * 128 + rg * 4) * 64 + cg * 8;
    #pragma unroll
    for (int r = 0; r < 4; r++) {
        float4* dst = (float4*)(g_y1 + base + r * 64);
        dst[0] = make_float4(acc[r][0],acc[r][1],acc[r][2],acc[r][3]);
        dst[1] = make_float4(acc[r][4],acc[r][5],acc[r][6],acc[r][7]);
    }
    #pragma unroll
    for (int i = 0; i < 8; i++) {
        int col = cg*8 + i;
        Red[rg*65 + col]        = acc[0][i]+acc[1][i]+acc[2][i]+acc[3][i];
        Red[2080 + rg*65 + col] = acc[0][i]*acc[0][i]+acc[1][i]*acc[1][i]
                                 +acc[2][i]*acc[2][i]+acc[3][i]*acc[3][i];
    }
    __syncthreads();
    if (t < 64) {
        float s = 0.f;
        for (int j = 0; j < 32; j++) s += Red[j*65 + t];
        g_part1[blockIdx.x*128 + t] = s;
    } else if (t < 128) {
        int col = t - 64; float s = 0.f;
        for (int j = 0; j < 32; j++) s += Red[2080 + j*65 + col];
        g_part1[blockIdx.x*128 + 64 + col] = s;
    }
}

// ------------- layer 2 fused: BN1+ReLU gather, GEMM 64->128, max/min over K ----
__global__ void __launch_bounds__(256) layer2_kernel(const float* __restrict__ w,
                                                     const float* __restrict__ bias) {
    extern __shared__ float sh[];
    float* XsT = sh;                   // [64][64] (64 rows = 2 (b,s) groups)
    float* Ws  = XsT + 64 * 64;        // [64][128]
    float* Red = Ws + 64 * 128;        // 4256: stride-133 rows, s1@0, s2@2128; reused for max/min
    __shared__ float sS[64], sH[64];
    int t = threadIdx.x;
    if (t < 64) { sS[t] = g_scale1[t]; sH[t] = g_shift1[t]; }
    for (int idx = t; idx < 64 * 128; idx += 256) {
        int c = idx >> 7, o = idx & 127;
        Ws[idx] = w[o * 64 + c];
    }
    __syncthreads();
    {
        int r = t & 63, quarter = t >> 6;
        size_t gr = (size_t)blockIdx.x * 64 + r;
        const float4* src = (const float4*)(g_y1 + gr * 64);
        for (int ch = quarter; ch < 16; ch += 4) {
            float4 v = src[ch]; int c0 = ch * 4;
            XsT[(c0+0)*64 + r] = fmaxf(0.f, fmaf(v.x, sS[c0],   sH[c0]));
            XsT[(c0+1)*64 + r] = fmaxf(0.f, fmaf(v.y, sS[c0+1], sH[c0+1]));
            XsT[(c0+2)*64 + r] = fmaxf(0.f, fmaf(v.z, sS[c0+2], sH[c0+2]));
            XsT[(c0+3)*64 + r] = fmaxf(0.f, fmaf(v.w, sS[c0+3], sH[c0+3]));
        }
    }
    __syncthreads();
    int rg = t >> 4, cg = t & 15;      // rows rg*4..+3 (of 64), cols cg*8..+7 (of 128)
    float acc[4][8];
    #pragma unroll
    for (int i = 0; i < 8; i++) {
        float bb = bias[cg*8+i];
        acc[0][i]=bb; acc[1][i]=bb; acc[2][i]=bb; acc[3][i]=bb;
    }
    for (int c = 0; c < 64; c++) {
        float4 a = *(const float4*)(XsT + c*64 + rg*4);
        const float4* wp = (const float4*)(Ws + c*128 + cg*8);
        float4 w0 = wp[0], w1 = wp[1];
        float av[4] = {a.x, a.y, a.z, a.w};
        float wv[8] = {w0.x,w0.y,w0.z,w0.w,w1.x,w1.y,w1.z,w1.w};
        #pragma unroll
        for (int r = 0; r < 4; r++)
            #pragma unroll
            for (int i = 0; i < 8; i++)
                acc[r][i] = fmaf(av[r], wv[i], acc[r][i]);
    }
    // ---- BN stats partials ----
    #pragma unroll
    for (int i = 0; i < 8; i++) {
        int col = cg*8 + i;
        Red[rg*133 + col]        = acc[0][i]+acc[1][i]+acc[2][i]+acc[3][i];
        Red[2128 + rg*133 + col] = acc[0][i]*acc[0][i]+acc[1][i]*acc[1][i]
                                  +acc[2][i]*acc[2][i]+acc[3][i]*acc[3][i];
    }
    __syncthreads();
    if (t < 128) {
        float s = 0.f;
        for (int j = 0; j < 16; j++) s += Red[j*133 + t];
        g_part2[blockIdx.x*256 + t] = s;
    } else {
        int col = t - 128; float s = 0.f;
        for (int j = 0; j < 16; j++) s += Red[2128 + j*133 + col];
        g_part2[blockIdx.x*256 + 128 + col] = s;
    }
    __syncthreads();
    // ---- pre-BN max/min over K within each 32-row group (rows rg*4..+3 same group) ----
    #pragma unroll
    for (int i = 0; i < 8; i++) {
        int col = cg*8 + i;
        float m = fmaxf(fmaxf(acc[0][i],acc[1][i]), fmaxf(acc[2][i],acc[3][i]));
        float n = fminf(fminf(acc[0][i],acc[1][i]), fminf(acc[2][i],acc[3][i]));
        Red[rg*133 + col]        = m;
        Red[2128 + rg*133 + col] = n;
    }
    __syncthreads();
    {
        int g = t >> 7, col = t & 127;          // g in {0,1}: rg 8g..8g+7
        float m = -3.4e38f, n = 3.4e38f;
        #pragma unroll
        for (int j = 0; j < 8; j++) {
            m = fmaxf(m, Red[(g*8+j)*133 + col]);
            n = fminf(n, Red[2128 + (g*8+j)*133 + col]);
        }
        size_t bs = (size_t)blockIdx.x * 2 + g;
        g_pmax[bs*128 + col] = m;
        g_pmin[bs*128 + col] = n;
    }
}

// ------------- BN stats: one block per channel -------------
__global__ void __launch_bounds__(256) stats_kernel(int layer, int nblk, int C,
                             const float* __restrict__ gamma, const float* __restrict__ beta) {
    int c = blockIdx.x;
    int t = threadIdx.x;
    const float* part = (layer == 0) ? g_part0 : (layer == 1) ? g_part1 : g_part2;
    float s1 = 0.f, s2 = 0.f;
    for (int bk = t; bk < nblk; bk += 256) {
        s1 += part[(size_t)bk*2*C + c];
        s2 += part[(size_t)bk*2*C + C + c];
    }
    __shared__ float r1[256], r2[256];
    r1[t] = s1; r2[t] = s2;
    __syncthreads();
    for (int off = 128; off >= 1; off >>= 1) {
        if (t < off) { r1[t] += r1[t+off]; r2[t] += r2[t+off]; }
        __syncthreads();
    }
    if (t == 0) {
        const float n = 524288.f;
        float mean = r1[0] / n;
        float var = r2[0] / n - mean * mean;
        float sc = gamma[c] * rsqrtf(var + EPSF);
        float sf = beta[c] - mean * sc;
        if (layer == 0)      { g_scale0[c] = sc; g_shift0[c] = sf; }
        else if (layer == 1) { g_scale1[c] = sc; g_shift1[c] = sf; }
        else                 { g_scale2[c] = sc; g_shift2[c] = sf; }
    }
}

// ------------- pool epilogue: BN2 on pooled extreme + ReLU, transposed write ----
__global__ void pool2_kernel(float* __restrict__ out, int pts_off) {
    int bs = blockIdx.x;        // b*1024 + s
    int c = threadIdx.x;        // 0..127
    float sc = g_scale2[c], sf = g_shift2[c];
    float v = (sc >= 0.f) ? g_pmax[(size_t)bs*128 + c] : g_pmin[(size_t)bs*128 + c];
    float m = fmaxf(fmaf(v, sc, sf), 0.f);
    out[pts_off + (bs >> 10) * (128 * 1024) + c * 1024 + (bs & 1023)] = m;
}

extern "C" void kernel_launch(void* const* d_in, const int* in_sizes, int n_in,
                              void* d_out, int out_size) {
    const float* xyz    = (const float*)d_in[0];
    const float* points = (const float*)d_in[1];
    const float* w0 = (const float*)d_in[2];  const float* b0  = (const float*)d_in[3];
    const float* g0 = (const float*)d_in[4];  const float* be0 = (const float*)d_in[5];
    const float* w1 = (const float*)d_in[6];  const float* b1  = (const float*)d_in[7];
    const float* g1 = (const float*)d_in[8];  const float* be1 = (const float*)d_in[9];
    const float* w2 = (const float*)d_in[10]; const float* b2  = (const float*)d_in[11];
    const float* g2 = (const float*)d_in[12]; const float* be2 = (const float*)d_in[13];
    float* out = (float*)d_out;

    int npts = B_ * 128 * S_;
    int pts_off = out_size - npts;
    if (pts_off < 0) pts_off = 0;

    cudaFuncSetAttribute(fps_kernel,    cudaFuncAttributeMaxDynamicSharedMemorySize, FPS_SMEM);
    cudaFuncSetAttribute(knn_kernel,    cudaFuncAttributeMaxDynamicSharedMemorySize, KNN_SMEM);
    cudaFuncSetAttribute(layer0_kernel, cudaFuncAttributeMaxDynamicSharedMemorySize, L0_SMEM);
    cudaFuncSetAttribute(layer1_kernel, cudaFuncAttributeMaxDynamicSharedMemorySize, L1_SMEM);
    cudaFuncSetAttribute(layer2_kernel, cudaFuncAttributeMaxDynamicSharedMemorySize, L2_SMEM);

    fps_kernel<<<B_, 1024, FPS_SMEM>>>(xyz);
    prep_kernel<<<(B_ * N_ + 255) / 256, 256>>>(xyz, out, pts_off > 0 ? 1 : 0);
    knn_kernel<<<B_ * 128, 256, KNN_SMEM>>>(xyz);
    layer0_kernel<<<4096, 256, L0_SMEM>>>(xyz, points, w0, b0);
    stats_kernel<<<64, 256>>>(0, 4096, 64, g0, be0);
    layer1_kernel<<<4096, 256, L1_SMEM>>>(w1, b1);
    stats_kernel<<<64, 256>>>(1, 4096, 64, g1, be1);
    layer2_kernel<<<8192, 256, L2_SMEM>>>(w2, b2);
    stats_kernel<<<128, 256>>>(2, 8192, 128, g2, be2);
    pool2_kernel<<<B_ * S_, 128>>>(out, pts_off);
}

// round 6
// speedup vs baseline: 1.5462x; 1.0021x over previous
#include <cuda_runtime.h>
#include <cstdint>

#define FULLMASK 0xffffffffu
namespace {
constexpr int B_ = 16, N_ = 4096, S_ = 1024, K_ = 32;
constexpr float EPSF = 1e-5f;
constexpr int FPS_SMEM = 3 * N_ * 4;                         // 49152
constexpr int KNN_SMEM = 4 * N_ * 4;                         // 65536
constexpr int L0_SMEM = (68 * 128 + 67 * 64 + 4160) * 4;     // XsT + Ws + Red
constexpr int L1_SMEM = (64 * 128 + 64 * 64 + 4160) * 4;
constexpr int L2_SMEM = (64 * 64 + 64 * 128 + 4256) * 4;
}

// ------------- scratch -------------
__device__ int      g_fps[B_ * S_];
__device__ float    g_newxyz[B_ * S_ * 3];
__device__ float    g_d2[B_ * N_];
__device__ int      g_nn[B_ * S_ * K_];
__device__ float    g_y0[B_ * S_ * K_ * 64];
__device__ float    g_y1[B_ * S_ * K_ * 64];
__device__ float    g_pmax[B_ * S_ * 128];
__device__ float    g_pmin[B_ * S_ * 128];
__device__ float    g_part0[4096 * 128];
__device__ float    g_part1[4096 * 128];
__device__ float    g_part2[8192 * 256];
__device__ float    g_scale0[64], g_shift0[64];
__device__ float    g_scale1[64], g_shift1[64];
__device__ float    g_scale2[128], g_shift2[128];

// ------------- KNN helpers (unchanged, they work) -------------
__device__ __forceinline__ void cmpswap(float& k, int& v, int j, bool dirAsc, int lane) {
    float ok = __shfl_xor_sync(FULLMASK, k, j);
    int   ov = __shfl_xor_sync(FULLMASK, v, j);
    bool takeOther = (((lane & j) == 0) == dirAsc) ? (ok < k) : (ok > k);
    if (takeOther) { k = ok; v = ov; }
}
__device__ __forceinline__ void bitonic_merge_asc(float& k, int& v, int lane) {
    #pragma unroll
    for (int j = 16; j > 0; j >>= 1) cmpswap(k, v, j, true, lane);
}
__device__ __forceinline__ void bitonic_sort_asc(float& k, int& v, int lane) {
    #pragma unroll
    for (int kk = 2; kk <= 16; kk <<= 1) {
        bool dir = ((lane & kk) == 0);
        #pragma unroll
        for (int j = kk >> 1; j > 0; j >>= 1) cmpswap(k, v, j, dir, lane);
    }
    bitonic_merge_asc(k, v, lane);
}

// ------------- FPS: one CTA per batch, REDUX reductions -------------
__global__ void __launch_bounds__(1024) fps_kernel(const float* __restrict__ xyz) {
    int b = blockIdx.x;
    extern __shared__ float sh[];
    float* sx = sh; float* sy = sh + N_; float* sz = sh + 2 * N_;
    __shared__ unsigned swv[2][32];
    __shared__ unsigned swi[2][32];
    int t = threadIdx.x, w = t >> 5, lane = t & 31;
    const float* X = xyz + (size_t)b * N_ * 3;
    for (int i = t; i < N_; i += 1024) { sx[i] = X[3*i]; sy[i] = X[3*i+1]; sz[i] = X[3*i+2]; }
    float dist[4];
    #pragma unroll
    for (int r = 0; r < 4; r++) dist[r] = 1e10f;
    int far = 0;
    __syncthreads();
    for (int it = 0; it < S_; ++it) {
        if (t == 0) g_fps[b * S_ + it] = far;
        float cx = sx[far], cy = sy[far], cz = sz[far];
        float bv = -1.0f; int bi = 0;
        #pragma unroll
        for (int r = 0; r < 4; r++) {
            int i = t + r * 1024;
            float dx = __fadd_rn(sx[i], -cx), dy = __fadd_rn(sy[i], -cy), dz = __fadd_rn(sz[i], -cz);
            float d = __fadd_rn(__fadd_rn(__fmul_rn(dx,dx), __fmul_rn(dy,dy)), __fmul_rn(dz,dz));
            float dm = fminf(dist[r], d);
            dist[r] = dm;
            if (dm > bv) { bv = dm; bi = i; }   // strict > keeps lowest index in-thread
        }
        // warp argmax: max value, then min index among ties (== argmax-first)
        unsigned db = __float_as_uint(bv);      // bv >= 0 after 4 updates
        unsigned mx = __reduce_max_sync(FULLMASK, db);
        unsigned cand = (db == mx) ? (unsigned)bi : 0xffffffffu;
        unsigned mi = __reduce_min_sync(FULLMASK, cand);
        int buf = it & 1;
        if (lane == 0) { swv[buf][w] = mx; swi[buf][w] = mi; }
        __syncthreads();
        unsigned v2 = swv[buf][lane];
        unsigned i2 = swi[buf][lane];
        unsigned mx2 = __reduce_max_sync(FULLMASK, v2);
        unsigned c2 = (v2 == mx2) ? i2 : 0xffffffffu;
        far = (int)__reduce_min_sync(FULLMASK, c2);
    }
}

// ------------- prep: ||x||^2 + gather new_xyz -------------
__global__ void prep_kernel(const float* __restrict__ xyz, float* __restrict__ out, int write_xyz) {
    int i = blockIdx.x * 256 + threadIdx.x;
    if (i < B_ * N_) {
        float x = xyz[3*i], y = xyz[3*i+1], z = xyz[3*i+2];
        g_d2[i] = __fadd_rn(__fadd_rn(__fmul_rn(x,x), __fmul_rn(y,y)), __fmul_rn(z,z));
    }
    if (i < B_ * S_) {
        int b = i >> 10, n = g_fps[i];
        const float* p = xyz + ((size_t)b * N_ + n) * 3;
        float px = p[0], py = p[1], pz = p[2];
        g_newxyz[3*i] = px; g_newxyz[3*i+1] = py; g_newxyz[3*i+2] = pz;
        if (write_xyz) { out[3*i] = px; out[3*i+1] = py; out[3*i+2] = pz; }
    }
}

// ------------- KNN: warp per query, bitonic top-32, exact fp32 -------------
__global__ void __launch_bounds__(256) knn_kernel(const float* __restrict__ xyz) {
    extern __shared__ float sh[];
    float* sx = sh; float* sy = sh + N_; float* sz = sh + 2*N_; float* sd = sh + 3*N_;
    int t = threadIdx.x;
    int b = blockIdx.x >> 7;
    int s0 = (blockIdx.x & 127) * 8;
    const float* X = xyz + (size_t)b * N_ * 3;
    for (int i = t; i < N_; i += 256) {
        sx[i] = X[3*i]; sy[i] = X[3*i+1]; sz[i] = X[3*i+2];
        sd[i] = g_d2[b * N_ + i];
    }
    __syncthreads();
    int w = t >> 5, lane = t & 31;
    int q = b * S_ + s0 + w;
    float qx = g_newxyz[3*q], qy = g_newxyz[3*q+1], qz = g_newxyz[3*q+2];
    float q2 = __fadd_rn(__fadd_rn(__fmul_rn(qx,qx), __fmul_rn(qy,qy)), __fmul_rn(qz,qz));
    float key = 3.0e38f; int kid = 0; float curmax = 3.0e38f;
    for (int c = 0; c < N_ / 32; c++) {
        int p = c * 32 + lane;
        float dot = __fadd_rn(__fadd_rn(__fmul_rn(qx, sx[p]),
                                        __fmul_rn(qy, sy[p])),
                              __fmul_rn(qz, sz[p]));
        float d = __fsub_rn(__fadd_rn(q2, sd[p]), __fmul_rn(2.0f, dot));
        if (!__ballot_sync(FULLMASK, d < curmax)) continue;
        float nk = d; int ni = p;
        bitonic_sort_asc(nk, ni, lane);
        float rk = __shfl_sync(FULLMASK, nk, 31 - lane);
        int   ri = __shfl_sync(FULLMASK, ni, 31 - lane);
        if (rk < key) { key = rk; kid = ri; }
        bitonic_merge_asc(key, kid, lane);
        curmax = __shfl_sync(FULLMASK, key, 31);
    }
    g_nn[q * K_ + lane] = kid;
}

// ------------- layer 0: gather + GEMM 67->64 (channel-major tile) -------------
__global__ void __launch_bounds__(256) layer0_kernel(const float* __restrict__ xyz,
                                                     const float* __restrict__ points,
                                                     const float* __restrict__ w,
                                                     const float* __restrict__ bias) {
    extern __shared__ float sh[];
    float* XsT = sh;                   // [68][128] channel-major
    float* Ws  = XsT + 68 * 128;       // [67][64]
    float* Red = Ws + 67 * 64;         // 4160: s1 @ rg*65+col, s2 @ 2080+...
    int t = threadIdx.x;
    for (int idx = t; idx < 67 * 64; idx += 256) {
        int cc = idx >> 6, o = idx & 63;
        int c = (cc < 64) ? (cc + 3) : (cc - 64);    // points-first channel order
        Ws[idx] = w[o * 67 + c];
    }
    {
        int r = t & 127, half = t >> 7;
        int gr = blockIdx.x * 128 + r;
        int q = gr >> 5, b = gr >> 15;
        int n = g_nn[gr];
        const float4* prow = (const float4*)(points + ((size_t)b * N_ + n) * 64);
        for (int ch = half; ch < 16; ch += 2) {
            float4 v = prow[ch];
            XsT[(ch*4+0)*128 + r] = v.x;
            XsT[(ch*4+1)*128 + r] = v.y;
            XsT[(ch*4+2)*128 + r] = v.z;
            XsT[(ch*4+3)*128 + r] = v.w;
        }
        if (half == 0) {
            const float* pp = xyz + ((size_t)b * N_ + n) * 3;
            XsT[64*128 + r] = __fadd_rn(pp[0], -g_newxyz[3*q]);
            XsT[65*128 + r] = __fadd_rn(pp[1], -g_newxyz[3*q+1]);
            XsT[66*128 + r] = __fadd_rn(pp[2], -g_newxyz[3*q+2]);
        }
    }
    __syncthreads();
    int rg = t >> 3, cg = t & 7;       // rows rg*4..+3, cols cg*8..+7
    float acc[4][8];
    #pragma unroll
    for (int i = 0; i < 8; i++) {
        float bb = bias[cg*8+i];
        acc[0][i]=bb; acc[1][i]=bb; acc[2][i]=bb; acc[3][i]=bb;
    }
    for (int c = 0; c < 67; c++) {
        float4 a = *(const float4*)(XsT + c*128 + rg*4);
        const float4* wp = (const float4*)(Ws + c*64 + cg*8);
        float4 w0 = wp[0], w1 = wp[1];
        float av[4] = {a.x, a.y, a.z, a.w};
        float wv[8] = {w0.x,w0.y,w0.z,w0.w,w1.x,w1.y,w1.z,w1.w};
        #pragma unroll
        for (int r = 0; r < 4; r++)
            #pragma unroll
            for (int i = 0; i < 8; i++)
                acc[r][i] = fmaf(av[r], wv[i], acc[r][i]);
    }
    size_t base = ((size_t)blockIdx.x * 128 + rg * 4) * 64 + cg * 8;
    #pragma unroll
    for (int r = 0; r < 4; r++) {
        float4* dst = (float4*)(g_y0 + base + r * 64);
        dst[0] = make_float4(acc[r][0],acc[r][1],acc[r][2],acc[r][3]);
        dst[1] = make_float4(acc[r][4],acc[r][5],acc[r][6],acc[r][7]);
    }
    #pragma unroll
    for (int i = 0; i < 8; i++) {
        int col = cg*8 + i;
        Red[rg*65 + col]        = acc[0][i]+acc[1][i]+acc[2][i]+acc[3][i];
        Red[2080 + rg*65 + col] = acc[0][i]*acc[0][i]+acc[1][i]*acc[1][i]
                                 +acc[2][i]*acc[2][i]+acc[3][i]*acc[3][i];
    }
    __syncthreads();
    if (t < 64) {
        float s = 0.f;
        for (int j = 0; j < 32; j++) s += Red[j*65 + t];
        g_part0[blockIdx.x*128 + t] = s;
    } else if (t < 128) {
        int col = t - 64; float s = 0.f;
        for (int j = 0; j < 32; j++) s += Red[2080 + j*65 + col];
        g_part0[blockIdx.x*128 + 64 + col] = s;
    }
}

// ------------- layer 1: BN0+ReLU fused gather, GEMM 64->64 -------------
__global__ void __launch_bounds__(256) layer1_kernel(const float* __restrict__ w,
                                                     const float* __restrict__ bias) {
    extern __shared__ float sh[];
    float* XsT = sh;                   // [64][128]
    float* Ws  = XsT + 64 * 128;       // [64][64]
    float* Red = Ws + 64 * 64;         // 4160
    __shared__ float sS[64], sH[64];
    int t = threadIdx.x;
    if (t < 64) { sS[t] = g_scale0[t]; sH[t] = g_shift0[t]; }
    for (int idx = t; idx < 64 * 64; idx += 256) {
        int c = idx >> 6, o = idx & 63;
        Ws[idx] = w[o * 64 + c];
    }
    __syncthreads();
    {
        int r = t & 127, half = t >> 7;
        size_t gr = (size_t)blockIdx.x * 128 + r;
        const float4* src = (const float4*)(g_y0 + gr * 64);
        for (int ch = half; ch < 16; ch += 2) {
            float4 v = src[ch]; int c0 = ch * 4;
            XsT[(c0+0)*128 + r] = fmaxf(0.f, fmaf(v.x, sS[c0],   sH[c0]));
            XsT[(c0+1)*128 + r] = fmaxf(0.f, fmaf(v.y, sS[c0+1], sH[c0+1]));
            XsT[(c0+2)*128 + r] = fmaxf(0.f, fmaf(v.z, sS[c0+2], sH[c0+2]));
            XsT[(c0+3)*128 + r] = fmaxf(0.f, fmaf(v.w, sS[c0+3], sH[c0+3]));
        }
    }
    __syncthreads();
    int rg = t >> 3, cg = t & 7;
    float acc[4][8];
    #pragma unroll
    for (int i = 0; i < 8; i++) {
        float bb = bias[cg*8+i];
        acc[0][i]=bb; acc[1][i]=bb; acc[2][i]=bb; acc[3][i]=bb;
    }
    for (int c = 0; c < 64; c++) {
        float4 a = *(const float4*)(XsT + c*128 + rg*4);
        const float4* wp = (const float4*)(Ws + c*64 + cg*8);
        float4 w0 = wp[0], w1 = wp[1];
        float av[4] = {a.x, a.y, a.z, a.w};
        float wv[8] = {w0.x,w0.y,w0.z,w0.w,w1.x,w1.y,w1.z,w1.w};
        #pragma unroll
        for (int r = 0; r < 4; r++)
            #pragma unroll
            for (int i = 0; i < 8; i++)
                acc[r][i] = fmaf(av[r], wv[i], acc[r][i]);
    }
    size_t base = ((size_t)blockIdx.x * 128 + rg * 4) * 64 + cg * 8;
    #pragma unroll
    for (int r = 0; r < 4; r++) {
        float4* dst = (float4*)(g_y1 + base + r * 64);
        dst[0] = make_float4(acc[r][0],acc[r][1],acc[r][2],acc[r][3]);
        dst[1] = make_float4(acc[r][4],acc[r][5],acc[r][6],acc[r][7]);
    }
    #pragma unroll
    for (int i = 0; i < 8; i++) {
        int col = cg*8 + i;
        Red[rg*65 + col]        = acc[0][i]+acc[1][i]+acc[2][i]+acc[3][i];
        Red[2080 + rg*65 + col] = acc[0][i]*acc[0][i]+acc[1][i]*acc[1][i]
                                 +acc[2][i]*acc[2][i]+acc[3][i]*acc[3][i];
    }
    __syncthreads();
    if (t < 64) {
        float s = 0.f;
        for (int j = 0; j < 32; j++) s += Red[j*65 + t];
        g_part1[blockIdx.x*128 + t] = s;
    } else if (t < 128) {
        int col = t - 64; float s = 0.f;
        for (int j = 0; j < 32; j++) s += Red[2080 + j*65 + col];
        g_part1[blockIdx.x*128 + 64 + col] = s;
    }
}

// ------------- layer 2 fused: BN1+ReLU gather, GEMM 64->128, max/min over K ----
__global__ void __launch_bounds__(256) layer2_kernel(const float* __restrict__ w,
                                                     const float* __restrict__ bias) {
    extern __shared__ float sh[];
    float* XsT = sh;                   // [64][64] (64 rows = 2 (b,s) groups)
    float* Ws  = XsT + 64 * 64;        // [64][128]
    float* Red = Ws + 64 * 128;        // 4256: stride-133 rows, s1@0, s2@2128; reused for max/min
    __shared__ float sS[64], sH[64];
    int t = threadIdx.x;
    if (t < 64) { sS[t] = g_scale1[t]; sH[t] = g_shift1[t]; }
    for (int idx = t; idx < 64 * 128; idx += 256) {
        int c = idx >> 7, o = idx & 127;
        Ws[idx] = w[o * 64 + c];
    }
    __syncthreads();
    {
        int r = t & 63, quarter = t >> 6;
        size_t gr = (size_t)blockIdx.x * 64 + r;
        const float4* src = (const float4*)(g_y1 + gr * 64);
        for (int ch = quarter; ch < 16; ch += 4) {
            float4 v = src[ch]; int c0 = ch * 4;
            XsT[(c0+0)*64 + r] = fmaxf(0.f, fmaf(v.x, sS[c0],   sH[c0]));
            XsT[(c0+1)*64 + r] = fmaxf(0.f, fmaf(v.y, sS[c0+1], sH[c0+1]));
            XsT[(c0+2)*64 + r] = fmaxf(0.f, fmaf(v.z, sS[c0+2], sH[c0+2]));
            XsT[(c0+3)*64 + r] = fmaxf(0.f, fmaf(v.w, sS[c0+3], sH[c0+3]));
        }
    }
    __syncthreads();
    int rg = t >> 4, cg = t & 15;      // rows rg*4..+3 (of 64), cols cg*8..+7 (of 128)
    float acc[4][8];
    #pragma unroll
    for (int i = 0; i < 8; i++) {
        float bb = bias[cg*8+i];
        acc[0][i]=bb; acc[1][i]=bb; acc[2][i]=bb; acc[3][i]=bb;
    }
    for (int c = 0; c < 64; c++) {
        float4 a = *(const float4*)(XsT + c*64 + rg*4);
        const float4* wp = (const float4*)(Ws + c*128 + cg*8);
        float4 w0 = wp[0], w1 = wp[1];
        float av[4] = {a.x, a.y, a.z, a.w};
        float wv[8] = {w0.x,w0.y,w0.z,w0.w,w1.x,w1.y,w1.z,w1.w};
        #pragma unroll
        for (int r = 0; r < 4; r++)
            #pragma unroll
            for (int i = 0; i < 8; i++)
                acc[r][i] = fmaf(av[r], wv[i], acc[r][i]);
    }
    // ---- BN stats partials ----
    #pragma unroll
    for (int i = 0; i < 8; i++) {
        int col = cg*8 + i;
        Red[rg*133 + col]        = acc[0][i]+acc[1][i]+acc[2][i]+acc[3][i];
        Red[2128 + rg*133 + col] = acc[0][i]*acc[0][i]+acc[1][i]*acc[1][i]
                                  +acc[2][i]*acc[2][i]+acc[3][i]*acc[3][i];
    }
    __syncthreads();
    if (t < 128) {
        float s = 0.f;
        for (int j = 0; j < 16; j++) s += Red[j*133 + t];
        g_part2[blockIdx.x*256 + t] = s;
    } else {
        int col = t - 128; float s = 0.f;
        for (int j = 0; j < 16; j++) s += Red[2128 + j*133 + col];
        g_part2[blockIdx.x*256 + 128 + col] = s;
    }
    __syncthreads();
    // ---- pre-BN max/min over K within each 32-row group (rows rg*4..+3 same group) ----
    #pragma unroll
    for (int i = 0; i < 8; i++) {
        int col = cg*8 + i;
        float m = fmaxf(fmaxf(acc[0][i],acc[1][i]), fmaxf(acc[2][i],acc[3][i]));
        float n = fminf(fminf(acc[0][i],acc[1][i]), fminf(acc[2][i],acc[3][i]));
        Red[rg*133 + col]        = m;
        Red[2128 + rg*133 + col] = n;
    }
    __syncthreads();
    {
        int g = t >> 7, col = t & 127;          // g in {0,1}: rg 8g..8g+7
        float m = -3.4e38f, n = 3.4e38f;
        #pragma unroll
        for (int j = 0; j < 8; j++) {
            m = fmaxf(m, Red[(g*8+j)*133 + col]);
            n = fminf(n, Red[2128 + (g*8+j)*133 + col]);
        }
        size_t bs = (size_t)blockIdx.x * 2 + g;
        g_pmax[bs*128 + col] = m;
        g_pmin[bs*128 + col] = n;
    }
}

// ------------- BN stats: one block per channel -------------
__global__ void __launch_bounds__(256) stats_kernel(int layer, int nblk, int C,
                             const float* __restrict__ gamma, const float* __restrict__ beta) {
    int c = blockIdx.x;
    int t = threadIdx.x;
    const float* part = (layer == 0) ? g_part0 : (layer == 1) ? g_part1 : g_part2;
    float s1 = 0.f, s2 = 0.f;
    for (int bk = t; bk < nblk; bk += 256) {
        s1 += part[(size_t)bk*2*C + c];
        s2 += part[(size_t)bk*2*C + C + c];
    }
    __shared__ float r1[256], r2[256];
    r1[t] = s1; r2[t] = s2;
    __syncthreads();
    for (int off = 128; off >= 1; off >>= 1) {
        if (t < off) { r1[t] += r1[t+off]; r2[t] += r2[t+off]; }
        __syncthreads();
    }
    if (t == 0) {
        const float n = 524288.f;
        float mean = r1[0] / n;
        float var = r2[0] / n - mean * mean;
        float sc = gamma[c] * rsqrtf(var + EPSF);
        float sf = beta[c] - mean * sc;
        if (layer == 0)      { g_scale0[c] = sc; g_shift0[c] = sf; }
        else if (layer == 1) { g_scale1[c] = sc; g_shift1[c] = sf; }
        else                 { g_scale2[c] = sc; g_shift2[c] = sf; }
    }
}

// ------------- pool epilogue: BN2 on pooled extreme + ReLU, transposed write ----
__global__ void pool2_kernel(float* __restrict__ out, int pts_off) {
    int bs = blockIdx.x;        // b*1024 + s
    int c = threadIdx.x;        // 0..127
    float sc = g_scale2[c], sf = g_shift2[c];
    float v = (sc >= 0.f) ? g_pmax[(size_t)bs*128 + c] : g_pmin[(size_t)bs*128 + c];
    float m = fmaxf(fmaf(v, sc, sf), 0.f);
    out[pts_off + (bs >> 10) * (128 * 1024) + c * 1024 + (bs & 1023)] = m;
}

extern "C" void kernel_launch(void* const* d_in, const int* in_sizes, int n_in,
                              void* d_out, int out_size) {
    const float* xyz    = (const float*)d_in[0];
    const float* points = (const float*)d_in[1];
    const float* w0 = (const float*)d_in[2];  const float* b0  = (const float*)d_in[3];
    const float* g0 = (const float*)d_in[4];  const float* be0 = (const float*)d_in[5];
    const float* w1 = (const float*)d_in[6];  const float* b1  = (const float*)d_in[7];
    const float* g1 = (const float*)d_in[8];  const float* be1 = (const float*)d_in[9];
    const float* w2 = (const float*)d_in[10]; const float* b2  = (const float*)d_in[11];
    const float* g2 = (const float*)d_in[12]; const float* be2 = (const float*)d_in[13];
    float* out = (float*)d_out;

    int npts = B_ * 128 * S_;
    int pts_off = out_size - npts;
    if (pts_off < 0) pts_off = 0;

    cudaFuncSetAttribute(fps_kernel,    cudaFuncAttributeMaxDynamicSharedMemorySize, FPS_SMEM);
    cudaFuncSetAttribute(knn_kernel,    cudaFuncAttributeMaxDynamicSharedMemorySize, KNN_SMEM);
    cudaFuncSetAttribute(layer0_kernel, cudaFuncAttributeMaxDynamicSharedMemorySize, L0_SMEM);
    cudaFuncSetAttribute(layer1_kernel, cudaFuncAttributeMaxDynamicSharedMemorySize, L1_SMEM);
    cudaFuncSetAttribute(layer2_kernel, cudaFuncAttributeMaxDynamicSharedMemorySize, L2_SMEM);

    fps_kernel<<<B_, 1024, FPS_SMEM>>>(xyz);
    prep_kernel<<<(B_ * N_ + 255) / 256, 256>>>(xyz, out, pts_off > 0 ? 1 : 0);
    knn_kernel<<<B_ * 128, 256, KNN_SMEM>>>(xyz);
    layer0_kernel<<<4096, 256, L0_SMEM>>>(xyz, points, w0, b0);
    stats_kernel<<<64, 256>>>(0, 4096, 64, g0, be0);
    layer1_kernel<<<4096, 256, L1_SMEM>>>(w1, b1);
    stats_kernel<<<64, 256>>>(1, 4096, 64, g1, be1);
    layer2_kernel<<<8192, 256, L2_SMEM>>>(w2, b2);
    stats_kernel<<<128, 256>>>(2, 8192, 128, g2, be2);
    pool2_kernel<<<B_ * S_, 128>>>(out, pts_off);
}

// round 7
// speedup vs baseline: 2.0910x; 1.3523x over previous
#include <cuda_runtime.h>
#include <cstdint>

#define FULLMASK 0xffffffffu
namespace {
constexpr int B_ = 16, N_ = 4096, S_ = 1024, K_ = 32;
constexpr float EPSF = 1e-5f;
constexpr int FPS_SMEM = 3 * N_ * 4;
constexpr int KNN_SMEM = 4 * N_ * 4;
constexpr int L0_SMEM = (68 * 128 + 67 * 64 + 2 * 16 * 65) * 4;    // 60288
constexpr int L1_SMEM = (64 * 128 + 64 * 64 + 2 * 16 * 65) * 4;    // 57472
constexpr int L2_SMEM = (64 * 128 + 64 * 128 + 2 * 16 * 129) * 4;  // 82048
}

// ------------- scratch -------------
__device__ int      g_fps[B_ * S_];
__device__ float    g_newxyz[B_ * S_ * 3];
__device__ float    g_d2[B_ * N_];
__device__ int      g_nn[B_ * S_ * K_];
__device__ float    g_y0[B_ * S_ * K_ * 64];
__device__ float    g_y1[B_ * S_ * K_ * 64];
__device__ float    g_pmax[B_ * S_ * 128];
__device__ float    g_pmin[B_ * S_ * 128];
__device__ float    g_part0[4096 * 128];
__device__ float    g_part1[4096 * 128];
__device__ float    g_part2[4096 * 256];
__device__ float    g_scale0[64], g_shift0[64];
__device__ float    g_scale1[64], g_shift1[64];
__device__ float    g_scale2[128], g_shift2[128];

// ------------- packed fp32x2 helpers (exact: two independent IEEE rn FMAs) ----
__device__ __forceinline__ unsigned long long pack2(float lo, float hi) {
    unsigned long long r;
    asm("mov.b64 %0, {%1, %2};" : "=l"(r) : "f"(lo), "f"(hi));
    return r;
}
__device__ __forceinline__ void fma2(unsigned long long& d, unsigned long long a, unsigned long long b) {
    asm("fma.rn.f32x2 %0, %1, %2, %0;" : "+l"(d) : "l"(a), "l"(b));
}
__device__ __forceinline__ float2 unpack2(unsigned long long v) {
    float lo, hi;
    asm("mov.b64 {%0, %1}, %2;" : "=f"(lo), "=f"(hi) : "l"(v));
    return make_float2(lo, hi);
}

// ------------- KNN helpers -------------
__device__ __forceinline__ void cmpswap(float& k, int& v, int j, bool dirAsc, int lane) {
    float ok = __shfl_xor_sync(FULLMASK, k, j);
    int   ov = __shfl_xor_sync(FULLMASK, v, j);
    bool takeOther = (((lane & j) == 0) == dirAsc) ? (ok < k) : (ok > k);
    if (takeOther) { k = ok; v = ov; }
}
__device__ __forceinline__ void bitonic_merge_asc(float& k, int& v, int lane) {
    #pragma unroll
    for (int j = 16; j > 0; j >>= 1) cmpswap(k, v, j, true, lane);
}
__device__ __forceinline__ void bitonic_sort_asc(float& k, int& v, int lane) {
    #pragma unroll
    for (int kk = 2; kk <= 16; kk <<= 1) {
        bool dir = ((lane & kk) == 0);
        #pragma unroll
        for (int j = kk >> 1; j > 0; j >>= 1) cmpswap(k, v, j, dir, lane);
    }
    bitonic_merge_asc(k, v, lane);
}

// ------------- FPS: one CTA per batch, points in registers -------------
__global__ void __launch_bounds__(1024) fps_kernel(const float* __restrict__ xyz) {
    int b = blockIdx.x;
    extern __shared__ float sh[];
    float* sx = sh; float* sy = sh + N_; float* sz = sh + 2 * N_;
    __shared__ unsigned swv[2][32];
    __shared__ unsigned swi[2][32];
    int t = threadIdx.x, w = t >> 5, lane = t & 31;
    const float* X = xyz + (size_t)b * N_ * 3;
    for (int i = t; i < N_; i += 1024) { sx[i] = X[3*i]; sy[i] = X[3*i+1]; sz[i] = X[3*i+2]; }
    __syncthreads();
    float rx[4], ry[4], rz[4], dist[4];
    #pragma unroll
    for (int r = 0; r < 4; r++) {
        int i = t + r * 1024;
        rx[r] = sx[i]; ry[r] = sy[i]; rz[r] = sz[i];
        dist[r] = 1e10f;
    }
    int far = 0;
    for (int it = 0; it < S_; ++it) {
        if (t == 0) g_fps[b * S_ + it] = far;
        float cx = sx[far], cy = sy[far], cz = sz[far];
        float bv = -1.0f; int bi = 0;
        #pragma unroll
        for (int r = 0; r < 4; r++) {
            float dx = __fadd_rn(rx[r], -cx), dy = __fadd_rn(ry[r], -cy), dz = __fadd_rn(rz[r], -cz);
            float d = __fadd_rn(__fadd_rn(__fmul_rn(dx,dx), __fmul_rn(dy,dy)), __fmul_rn(dz,dz));
            float dm = fminf(dist[r], d);
            dist[r] = dm;
            if (dm > bv) { bv = dm; bi = t + r * 1024; }   // strict >: lowest index in-thread
        }
        unsigned db = __float_as_uint(bv);
        unsigned mx = __reduce_max_sync(FULLMASK, db);
        unsigned cand = (db == mx) ? (unsigned)bi : 0xffffffffu;
        unsigned mi = __reduce_min_sync(FULLMASK, cand);
        int buf = it & 1;
        if (lane == 0) { swv[buf][w] = mx; swi[buf][w] = mi; }
        __syncthreads();
        unsigned v2 = swv[buf][lane];
        unsigned i2 = swi[buf][lane];
        unsigned mx2 = __reduce_max_sync(FULLMASK, v2);
        unsigned c2 = (v2 == mx2) ? i2 : 0xffffffffu;
        far = (int)__reduce_min_sync(FULLMASK, c2);
    }
}

// ------------- prep: ||x||^2 + gather new_xyz -------------
__global__ void prep_kernel(const float* __restrict__ xyz, float* __restrict__ out, int write_xyz) {
    int i = blockIdx.x * 256 + threadIdx.x;
    if (i < B_ * N_) {
        float x = xyz[3*i], y = xyz[3*i+1], z = xyz[3*i+2];
        g_d2[i] = __fadd_rn(__fadd_rn(__fmul_rn(x,x), __fmul_rn(y,y)), __fmul_rn(z,z));
    }
    if (i < B_ * S_) {
        int b = i >> 10, n = g_fps[i];
        const float* p = xyz + ((size_t)b * N_ + n) * 3;
        float px = p[0], py = p[1], pz = p[2];
        g_newxyz[3*i] = px; g_newxyz[3*i+1] = py; g_newxyz[3*i+2] = pz;
        if (write_xyz) { out[3*i] = px; out[3*i+1] = py; out[3*i+2] = pz; }
    }
}

// ------------- KNN: warp per query, bitonic top-32, exact fp32 -------------
__global__ void __launch_bounds__(256) knn_kernel(const float* __restrict__ xyz) {
    extern __shared__ float sh[];
    float* sx = sh; float* sy = sh + N_; float* sz = sh + 2*N_; float* sd = sh + 3*N_;
    int t = threadIdx.x;
    int b = blockIdx.x >> 7;
    int s0 = (blockIdx.x & 127) * 8;
    const float* X = xyz + (size_t)b * N_ * 3;
    for (int i = t; i < N_; i += 256) {
        sx[i] = X[3*i]; sy[i] = X[3*i+1]; sz[i] = X[3*i+2];
        sd[i] = g_d2[b * N_ + i];
    }
    __syncthreads();
    int w = t >> 5, lane = t & 31;
    int q = b * S_ + s0 + w;
    float qx = g_newxyz[3*q], qy = g_newxyz[3*q+1], qz = g_newxyz[3*q+2];
    float q2 = __fadd_rn(__fadd_rn(__fmul_rn(qx,qx), __fmul_rn(qy,qy)), __fmul_rn(qz,qz));
    float key = 3.0e38f; int kid = 0; float curmax = 3.0e38f;
    for (int c = 0; c < N_ / 32; c++) {
        int p = c * 32 + lane;
        float dot = __fadd_rn(__fadd_rn(__fmul_rn(qx, sx[p]),
                                        __fmul_rn(qy, sy[p])),
                              __fmul_rn(qz, sz[p]));
        float d = __fsub_rn(__fadd_rn(q2, sd[p]), __fmul_rn(2.0f, dot));
        if (!__ballot_sync(FULLMASK, d < curmax)) continue;
        float nk = d; int ni = p;
        bitonic_sort_asc(nk, ni, lane);
        float rk = __shfl_sync(FULLMASK, nk, 31 - lane);
        int   ri = __shfl_sync(FULLMASK, ni, 31 - lane);
        if (rk < key) { key = rk; kid = ri; }
        bitonic_merge_asc(key, kid, lane);
        curmax = __shfl_sync(FULLMASK, key, 31);
    }
    g_nn[q * K_ + lane] = kid;
}

// ------------- layer 0: gather + GEMM 67->64, 8x8 tiles, FFMA2 -------------
__global__ void __launch_bounds__(128) layer0_kernel(const float* __restrict__ xyz,
                                                     const float* __restrict__ points,
                                                     const float* __restrict__ w,
                                                     const float* __restrict__ bias) {
    extern __shared__ float sh[];
    float* XsT = sh;                   // [68][128]
    float* Ws  = XsT + 68 * 128;       // [67][64]
    float* Red = Ws + 67 * 64;         // 2 x [16][65]
    int t = threadIdx.x;
    for (int idx = t; idx < 67 * 64; idx += 128) {
        int cc = idx >> 6, o = idx & 63;
        int c = (cc < 64) ? (cc + 3) : (cc - 64);
        Ws[idx] = w[o * 67 + c];
    }
    {
        int r = t;
        int gr = blockIdx.x * 128 + r;
        int q = gr >> 5, b = gr >> 15;
        int n = g_nn[gr];
        const float4* prow = (const float4*)(points + ((size_t)b * N_ + n) * 64);
        #pragma unroll 4
        for (int ch = 0; ch < 16; ch++) {
            float4 v = prow[ch];
            XsT[(ch*4+0)*128 + r] = v.x;
            XsT[(ch*4+1)*128 + r] = v.y;
            XsT[(ch*4+2)*128 + r] = v.z;
            XsT[(ch*4+3)*128 + r] = v.w;
        }
        const float* pp = xyz + ((size_t)b * N_ + n) * 3;
        XsT[64*128 + r] = __fadd_rn(pp[0], -g_newxyz[3*q]);
        XsT[65*128 + r] = __fadd_rn(pp[1], -g_newxyz[3*q+1]);
        XsT[66*128 + r] = __fadd_rn(pp[2], -g_newxyz[3*q+2]);
    }
    __syncthreads();
    int rg = t >> 3, cg = t & 7;       // rows rg*8..+7, cols cg*8..+7
    unsigned long long acc[8][4];
    #pragma unroll
    for (int j = 0; j < 4; j++) {
        unsigned long long bb = pack2(bias[cg*8+2*j], bias[cg*8+2*j+1]);
        #pragma unroll
        for (int r = 0; r < 8; r++) acc[r][j] = bb;
    }
    for (int c = 0; c < 67; c++) {
        const float4* ap = (const float4*)(XsT + c*128 + rg*8);
        float4 a0 = ap[0], a1 = ap[1];
        const float4* wp = (const float4*)(Ws + c*64 + cg*8);
        float4 w0 = wp[0], w1 = wp[1];
        unsigned long long wv[4] = {pack2(w0.x,w0.y), pack2(w0.z,w0.w),
                                    pack2(w1.x,w1.y), pack2(w1.z,w1.w)};
        float av[8] = {a0.x,a0.y,a0.z,a0.w,a1.x,a1.y,a1.z,a1.w};
        #pragma unroll
        for (int r = 0; r < 8; r++) {
            unsigned long long aa = pack2(av[r], av[r]);
            #pragma unroll
            for (int j = 0; j < 4; j++) fma2(acc[r][j], aa, wv[j]);
        }
    }
    float s1[8], s2[8];
    #pragma unroll
    for (int i = 0; i < 8; i++) { s1[i] = 0.f; s2[i] = 0.f; }
    #pragma unroll
    for (int r = 0; r < 8; r++) {
        float f[8];
        #pragma unroll
        for (int j = 0; j < 4; j++) { float2 p = unpack2(acc[r][j]); f[2*j] = p.x; f[2*j+1] = p.y; }
        float4* dst = (float4*)(g_y0 + ((size_t)blockIdx.x * 128 + rg*8 + r) * 64 + cg*8);
        dst[0] = make_float4(f[0],f[1],f[2],f[3]);
        dst[1] = make_float4(f[4],f[5],f[6],f[7]);
        #pragma unroll
        for (int i = 0; i < 8; i++) { s1[i] += f[i]; s2[i] += f[i]*f[i]; }
    }
    #pragma unroll
    for (int i = 0; i < 8; i++) {
        int col = cg*8 + i;
        Red[rg*65 + col]        = s1[i];
        Red[1040 + rg*65 + col] = s2[i];
    }
    __syncthreads();
    if (t < 64) {
        float s = 0.f;
        #pragma unroll 4
        for (int j = 0; j < 16; j++) s += Red[j*65 + t];
        g_part0[blockIdx.x*128 + t] = s;
    } else {
        int col = t - 64; float s = 0.f;
        #pragma unroll 4
        for (int j = 0; j < 16; j++) s += Red[1040 + j*65 + col];
        g_part0[blockIdx.x*128 + 64 + col] = s;
    }
}

// ------------- layer 1: BN0+ReLU fused gather, GEMM 64->64, FFMA2 -------------
__global__ void __launch_bounds__(128) layer1_kernel(const float* __restrict__ w,
                                                     const float* __restrict__ bias) {
    extern __shared__ float sh[];
    float* XsT = sh;                   // [64][128]
    float* Ws  = XsT + 64 * 128;       // [64][64]
    float* Red = Ws + 64 * 64;         // 2 x [16][65]
    __shared__ float sS[64], sH[64];
    int t = threadIdx.x;
    if (t < 64) { sS[t] = g_scale0[t]; sH[t] = g_shift0[t]; }
    for (int idx = t; idx < 64 * 64; idx += 128) {
        int c = idx >> 6, o = idx & 63;
        Ws[idx] = w[o * 64 + c];
    }
    __syncthreads();
    {
        int r = t;
        size_t gr = (size_t)blockIdx.x * 128 + r;
        const float4* src = (const float4*)(g_y0 + gr * 64);
        #pragma unroll 4
        for (int ch = 0; ch < 16; ch++) {
            float4 v = src[ch]; int c0 = ch * 4;
            XsT[(c0+0)*128 + r] = fmaxf(0.f, fmaf(v.x, sS[c0],   sH[c0]));
            XsT[(c0+1)*128 + r] = fmaxf(0.f, fmaf(v.y, sS[c0+1], sH[c0+1]));
            XsT[(c0+2)*128 + r] = fmaxf(0.f, fmaf(v.z, sS[c0+2], sH[c0+2]));
            XsT[(c0+3)*128 + r] = fmaxf(0.f, fmaf(v.w, sS[c0+3], sH[c0+3]));
        }
    }
    __syncthreads();
    int rg = t >> 3, cg = t & 7;
    unsigned long long acc[8][4];
    #pragma unroll
    for (int j = 0; j < 4; j++) {
        unsigned long long bb = pack2(bias[cg*8+2*j], bias[cg*8+2*j+1]);
        #pragma unroll
        for (int r = 0; r < 8; r++) acc[r][j] = bb;
    }
    for (int c = 0; c < 64; c++) {
        const float4* ap = (const float4*)(XsT + c*128 + rg*8);
        float4 a0 = ap[0], a1 = ap[1];
        const float4* wp = (const float4*)(Ws + c*64 + cg*8);
        float4 w0 = wp[0], w1 = wp[1];
        unsigned long long wv[4] = {pack2(w0.x,w0.y), pack2(w0.z,w0.w),
                                    pack2(w1.x,w1.y), pack2(w1.z,w1.w)};
        float av[8] = {a0.x,a0.y,a0.z,a0.w,a1.x,a1.y,a1.z,a1.w};
        #pragma unroll
        for (int r = 0; r < 8; r++) {
            unsigned long long aa = pack2(av[r], av[r]);
            #pragma unroll
            for (int j = 0; j < 4; j++) fma2(acc[r][j], aa, wv[j]);
        }
    }
    float s1[8], s2[8];
    #pragma unroll
    for (int i = 0; i < 8; i++) { s1[i] = 0.f; s2[i] = 0.f; }
    #pragma unroll
    for (int r = 0; r < 8; r++) {
        float f[8];
        #pragma unroll
        for (int j = 0; j < 4; j++) { float2 p = unpack2(acc[r][j]); f[2*j] = p.x; f[2*j+1] = p.y; }
        float4* dst = (float4*)(g_y1 + ((size_t)blockIdx.x * 128 + rg*8 + r) * 64 + cg*8);
        dst[0] = make_float4(f[0],f[1],f[2],f[3]);
        dst[1] = make_float4(f[4],f[5],f[6],f[7]);
        #pragma unroll
        for (int i = 0; i < 8; i++) { s1[i] += f[i]; s2[i] += f[i]*f[i]; }
    }
    #pragma unroll
    for (int i = 0; i < 8; i++) {
        int col = cg*8 + i;
        Red[rg*65 + col]        = s1[i];
        Red[1040 + rg*65 + col] = s2[i];
    }
    __syncthreads();
    if (t < 64) {
        float s = 0.f;
        #pragma unroll 4
        for (int j = 0; j < 16; j++) s += Red[j*65 + t];
        g_part1[blockIdx.x*128 + t] = s;
    } else {
        int col = t - 64; float s = 0.f;
        #pragma unroll 4
        for (int j = 0; j < 16; j++) s += Red[1040 + j*65 + col];
        g_part1[blockIdx.x*128 + 64 + col] = s;
    }
}

// ------------- layer 2 fused: BN1+ReLU gather, GEMM 64->128, max/min over K ----
__global__ void __launch_bounds__(256) layer2_kernel(const float* __restrict__ w,
                                                     const float* __restrict__ bias) {
    extern __shared__ float sh[];
    float* XsT = sh;                   // [64][128]
    float* Ws  = XsT + 64 * 128;       // [64][128]
    float* Red = Ws + 64 * 128;        // 2 x [16][129]
    __shared__ float sS[64], sH[64];
    int t = threadIdx.x;
    if (t < 64) { sS[t] = g_scale1[t]; sH[t] = g_shift1[t]; }
    for (int idx = t; idx < 64 * 128; idx += 256) {
        int c = idx >> 7, o = idx & 127;
        Ws[idx] = w[o * 64 + c];
    }
    __syncthreads();
    {
        int r = t & 127, half = t >> 7;
        size_t gr = (size_t)blockIdx.x * 128 + r;
        const float4* src = (const float4*)(g_y1 + gr * 64);
        for (int ch = half; ch < 16; ch += 2) {
            float4 v = src[ch]; int c0 = ch * 4;
            XsT[(c0+0)*128 + r] = fmaxf(0.f, fmaf(v.x, sS[c0],   sH[c0]));
            XsT[(c0+1)*128 + r] = fmaxf(0.f, fmaf(v.y, sS[c0+1], sH[c0+1]));
            XsT[(c0+2)*128 + r] = fmaxf(0.f, fmaf(v.z, sS[c0+2], sH[c0+2]));
            XsT[(c0+3)*128 + r] = fmaxf(0.f, fmaf(v.w, sS[c0+3], sH[c0+3]));
        }
    }
    __syncthreads();
    int rg = t >> 4, cg = t & 15;      // rows rg*8..+7 (128), cols cg*8..+7 (128)
    unsigned long long acc[8][4];
    #pragma unroll
    for (int j = 0; j < 4; j++) {
        unsigned long long bb = pack2(bias[cg*8+2*j], bias[cg*8+2*j+1]);
        #pragma unroll
        for (int r = 0; r < 8; r++) acc[r][j] = bb;
    }
    for (int c = 0; c < 64; c++) {
        const float4* ap = (const float4*)(XsT + c*128 + rg*8);
        float4 a0 = ap[0], a1 = ap[1];
        const float4* wp = (const float4*)(Ws + c*128 + cg*8);
        float4 w0 = wp[0], w1 = wp[1];
        unsigned long long wv[4] = {pack2(w0.x,w0.y), pack2(w0.z,w0.w),
                                    pack2(w1.x,w1.y), pack2(w1.z,w1.w)};
        float av[8] = {a0.x,a0.y,a0.z,a0.w,a1.x,a1.y,a1.z,a1.w};
        #pragma unroll
        for (int r = 0; r < 8; r++) {
            unsigned long long aa = pack2(av[r], av[r]);
            #pragma unroll
            for (int j = 0; j < 4; j++) fma2(acc[r][j], aa, wv[j]);
        }
    }
    // unpack, stats + max/min over this thread's 8 rows (all in group rg>>2)
    float s1[8], s2[8], mx[8], mn[8];
    #pragma unroll
    for (int i = 0; i < 8; i++) { s1[i]=0.f; s2[i]=0.f; mx[i]=-3.4e38f; mn[i]=3.4e38f; }
    #pragma unroll
    for (int r = 0; r < 8; r++) {
        float f[8];
        #pragma unroll
        for (int j = 0; j < 4; j++) { float2 p = unpack2(acc[r][j]); f[2*j] = p.x; f[2*j+1] = p.y; }
        #pragma unroll
        for (int i = 0; i < 8; i++) {
            s1[i] += f[i]; s2[i] += f[i]*f[i];
            mx[i] = fmaxf(mx[i], f[i]); mn[i] = fminf(mn[i], f[i]);
        }
    }
    #pragma unroll
    for (int i = 0; i < 8; i++) {
        int col = cg*8 + i;
        Red[rg*129 + col]        = s1[i];
        Red[2064 + rg*129 + col] = s2[i];
    }
    __syncthreads();
    if (t < 128) {
        float s = 0.f;
        #pragma unroll 4
        for (int j = 0; j < 16; j++) s += Red[j*129 + t];
        g_part2[blockIdx.x*256 + t] = s;
    } else {
        int col = t - 128; float s = 0.f;
        #pragma unroll 4
        for (int j = 0; j < 16; j++) s += Red[2064 + j*129 + col];
        g_part2[blockIdx.x*256 + 128 + col] = s;
    }
    __syncthreads();
    #pragma unroll
    for (int i = 0; i < 8; i++) {
        int col = cg*8 + i;
        Red[rg*129 + col]        = mx[i];
        Red[2064 + rg*129 + col] = mn[i];
    }
    __syncthreads();
    {
        // 4 (b,s) groups of 32 rows each: group g covers rg 4g..4g+3
        int col = t & 127, which = t >> 7;   // which: 0=max, 1=min
        #pragma unroll
        for (int g = 0; g < 4; g++) {
            size_t bs = (size_t)blockIdx.x * 4 + g;
            if (which == 0) {
                float m = -3.4e38f;
                #pragma unroll
                for (int j = 0; j < 4; j++) m = fmaxf(m, Red[(g*4+j)*129 + col]);
                g_pmax[bs*128 + col] = m;
            } else {
                float n = 3.4e38f;
                #pragma unroll
                for (int j = 0; j < 4; j++) n = fminf(n, Red[2064 + (g*4+j)*129 + col]);
                g_pmin[bs*128 + col] = n;
            }
        }
    }
}

// ------------- BN stats -------------
__global__ void __launch_bounds__(256) stats_kernel(int layer, int nblk, int C,
                             const float* __restrict__ gamma, const float* __restrict__ beta) {
    int c = blockIdx.x;
    int t = threadIdx.x;
    const float* part = (layer == 0) ? g_part0 : (layer == 1) ? g_part1 : g_part2;
    float s1 = 0.f, s2 = 0.f;
    for (int bk = t; bk < nblk; bk += 256) {
        s1 += part[(size_t)bk*2*C + c];
        s2 += part[(size_t)bk*2*C + C + c];
    }
    __shared__ float r1[256], r2[256];
    r1[t] = s1; r2[t] = s2;
    __syncthreads();
    for (int off = 128; off >= 1; off >>= 1) {
        if (t < off) { r1[t] += r1[t+off]; r2[t] += r2[t+off]; }
        __syncthreads();
    }
    if (t == 0) {
        const float n = 524288.f;
        float mean = r1[0] / n;
        float var = r2[0] / n - mean * mean;
        float sc = gamma[c] * rsqrtf(var + EPSF);
        float sf = beta[c] - mean * sc;
        if (layer == 0)      { g_scale0[c] = sc; g_shift0[c] = sf; }
        else if (layer == 1) { g_scale1[c] = sc; g_shift1[c] = sf; }
        else                 { g_scale2[c] = sc; g_shift2[c] = sf; }
    }
}

// ------------- pool epilogue -------------
__global__ void pool2_kernel(float* __restrict__ out, int pts_off) {
    int bs = blockIdx.x;
    int c = threadIdx.x;
    float sc = g_scale2[c], sf = g_shift2[c];
    float v = (sc >= 0.f) ? g_pmax[(size_t)bs*128 + c] : g_pmin[(size_t)bs*128 + c];
    float m = fmaxf(fmaf(v, sc, sf), 0.f);
    out[pts_off + (bs >> 10) * (128 * 1024) + c * 1024 + (bs & 1023)] = m;
}

extern "C" void kernel_launch(void* const* d_in, const int* in_sizes, int n_in,
                              void* d_out, int out_size) {
    const float* xyz    = (const float*)d_in[0];
    const float* points = (const float*)d_in[1];
    const float* w0 = (const float*)d_in[2];  const float* b0  = (const float*)d_in[3];
    const float* g0 = (const float*)d_in[4];  const float* be0 = (const float*)d_in[5];
    const float* w1 = (const float*)d_in[6];  const float* b1  = (const float*)d_in[7];
    const float* g1 = (const float*)d_in[8];  const float* be1 = (const float*)d_in[9];
    const float* w2 = (const float*)d_in[10]; const float* b2  = (const float*)d_in[11];
    const float* g2 = (const float*)d_in[12]; const float* be2 = (const float*)d_in[13];
    float* out = (float*)d_out;

    int npts = B_ * 128 * S_;
    int pts_off = out_size - npts;
    if (pts_off < 0) pts_off = 0;

    cudaFuncSetAttribute(fps_kernel,    cudaFuncAttributeMaxDynamicSharedMemorySize, FPS_SMEM);
    cudaFuncSetAttribute(knn_kernel,    cudaFuncAttributeMaxDynamicSharedMemorySize, KNN_SMEM);
    cudaFuncSetAttribute(layer0_kernel, cudaFuncAttributeMaxDynamicSharedMemorySize, L0_SMEM);
    cudaFuncSetAttribute(layer1_kernel, cudaFuncAttributeMaxDynamicSharedMemorySize, L1_SMEM);
    cudaFuncSetAttribute(layer2_kernel, cudaFuncAttributeMaxDynamicSharedMemorySize, L2_SMEM);

    fps_kernel<<<B_, 1024, FPS_SMEM>>>(xyz);
    prep_kernel<<<(B_ * N_ + 255) / 256, 256>>>(xyz, out, pts_off > 0 ? 1 : 0);
    knn_kernel<<<B_ * 128, 256, KNN_SMEM>>>(xyz);
    layer0_kernel<<<4096, 128, L0_SMEM>>>(xyz, points, w0, b0);
    stats_kernel<<<64, 256>>>(0, 4096, 64, g0, be0);
    layer1_kernel<<<4096, 128, L1_SMEM>>>(w1, b1);
    stats_kernel<<<64, 256>>>(1, 4096, 64, g1, be1);
    layer2_kernel<<<4096, 256, L2_SMEM>>>(w2, b2);
    stats_kernel<<<128, 256>>>(2, 4096, 128, g2, be2);
    pool2_kernel<<<B_ * S_, 128>>>(out, pts_off);
}

// round 8
// speedup vs baseline: 2.2201x; 1.0618x over previous
#include <cuda_runtime.h>
#include <cstdint>

#define FULLMASK 0xffffffffu
typedef unsigned long long ull;
namespace {
constexpr int B_ = 16, N_ = 4096, S_ = 1024, K_ = 32;
constexpr float EPSF = 1e-5f;
constexpr int FPS_SMEM = 3 * N_ * 4;
constexpr int KNN_SMEM = 4 * N_ * 4;
constexpr int L0_SMEM = (68 * 256 + 67 * 64 + 2 * 16 * 65) * 4;    // 95104
constexpr int L1_SMEM = (64 * 256 + 64 * 64 + 2 * 16 * 65) * 4;    // 90240
constexpr int L2_SMEM = (64 * 256 + 64 * 128 + 2 * 16 * 129) * 4;  // 114816
}

// ------------- scratch -------------
__device__ int      g_fps[B_ * S_];
__device__ float    g_newxyz[B_ * S_ * 3];
__device__ float    g_d2[B_ * N_];
__device__ int      g_nn[B_ * S_ * K_];
__device__ float    g_y0[B_ * S_ * K_ * 64];
__device__ float    g_y1[B_ * S_ * K_ * 64];
__device__ float    g_pmax[B_ * S_ * 128];
__device__ float    g_pmin[B_ * S_ * 128];
__device__ float    g_part0[2048 * 128];
__device__ float    g_part1[2048 * 128];
__device__ float    g_part2[2048 * 256];
__device__ float    g_scale0[64], g_shift0[64];
__device__ float    g_scale1[64], g_shift1[64];
__device__ float    g_scale2[128], g_shift2[128];

// ------------- packed fp32x2 helpers (bit-exact: independent IEEE rn lanes) ----
__device__ __forceinline__ ull pack2(float lo, float hi) {
    ull r;
    asm("mov.b64 %0, {%1, %2};" : "=l"(r) : "f"(lo), "f"(hi));
    return r;
}
__device__ __forceinline__ void fma2(ull& d, ull a, ull b) {
    asm("fma.rn.f32x2 %0, %1, %2, %0;" : "+l"(d) : "l"(a), "l"(b));
}
__device__ __forceinline__ ull add2(ull a, ull b) {
    ull r; asm("add.rn.f32x2 %0, %1, %2;" : "=l"(r) : "l"(a), "l"(b)); return r;
}
__device__ __forceinline__ ull mul2(ull a, ull b) {
    ull r; asm("mul.rn.f32x2 %0, %1, %2;" : "=l"(r) : "l"(a), "l"(b)); return r;
}
__device__ __forceinline__ float2 unpack2(ull v) {
    float lo, hi;
    asm("mov.b64 {%0, %1}, %2;" : "=f"(lo), "=f"(hi) : "l"(v));
    return make_float2(lo, hi);
}

// ------------- KNN helpers -------------
__device__ __forceinline__ void cmpswap(float& k, int& v, int j, bool dirAsc, int lane) {
    float ok = __shfl_xor_sync(FULLMASK, k, j);
    int   ov = __shfl_xor_sync(FULLMASK, v, j);
    bool takeOther = (((lane & j) == 0) == dirAsc) ? (ok < k) : (ok > k);
    if (takeOther) { k = ok; v = ov; }
}
__device__ __forceinline__ void bitonic_merge_asc(float& k, int& v, int lane) {
    #pragma unroll
    for (int j = 16; j > 0; j >>= 1) cmpswap(k, v, j, true, lane);
}
__device__ __forceinline__ void bitonic_sort_asc(float& k, int& v, int lane) {
    #pragma unroll
    for (int kk = 2; kk <= 16; kk <<= 1) {
        bool dir = ((lane & kk) == 0);
        #pragma unroll
        for (int j = kk >> 1; j > 0; j >>= 1) cmpswap(k, v, j, dir, lane);
    }
    bitonic_merge_asc(k, v, lane);
}

// ------------- FPS: one CTA per batch, packed f32x2 distance math -------------
__global__ void __launch_bounds__(1024) fps_kernel(const float* __restrict__ xyz) {
    int b = blockIdx.x;
    extern __shared__ float sh[];
    float* sx = sh; float* sy = sh + N_; float* sz = sh + 2 * N_;
    __shared__ unsigned swv[2][32];
    __shared__ unsigned swi[2][32];
    int t = threadIdx.x, w = t >> 5, lane = t & 31;
    const float* X = xyz + (size_t)b * N_ * 3;
    for (int i = t; i < N_; i += 1024) { sx[i] = X[3*i]; sy[i] = X[3*i+1]; sz[i] = X[3*i+2]; }
    __syncthreads();
    ull rxp[2], ryp[2], rzp[2];
    float dist[4];
    #pragma unroll
    for (int p = 0; p < 2; p++) {
        int i0 = t + (2*p) * 1024, i1 = t + (2*p+1) * 1024;
        rxp[p] = pack2(sx[i0], sx[i1]);
        ryp[p] = pack2(sy[i0], sy[i1]);
        rzp[p] = pack2(sz[i0], sz[i1]);
        dist[2*p] = 1e10f; dist[2*p+1] = 1e10f;
    }
    int far = 0;
    for (int it = 0; it < S_; ++it) {
        if (t == 0) g_fps[b * S_ + it] = far;
        float cx = sx[far], cy = sy[far], cz = sz[far];
        ull ncx = pack2(-cx, -cx), ncy = pack2(-cy, -cy), ncz = pack2(-cz, -cz);
        float bv = -1.0f; int bi = 0;
        #pragma unroll
        for (int p = 0; p < 2; p++) {
            ull dx = add2(rxp[p], ncx);
            ull dy = add2(ryp[p], ncy);
            ull dz = add2(rzp[p], ncz);
            ull s = add2(add2(mul2(dx,dx), mul2(dy,dy)), mul2(dz,dz));
            float2 d = unpack2(s);
            float dm0 = fminf(dist[2*p], d.x);   dist[2*p] = dm0;
            if (dm0 > bv) { bv = dm0; bi = t + (2*p) * 1024; }
            float dm1 = fminf(dist[2*p+1], d.y); dist[2*p+1] = dm1;
            if (dm1 > bv) { bv = dm1; bi = t + (2*p+1) * 1024; }
        }
        unsigned db = __float_as_uint(bv);
        unsigned mx = __reduce_max_sync(FULLMASK, db);
        unsigned cand = (db == mx) ? (unsigned)bi : 0xffffffffu;
        unsigned mi = __reduce_min_sync(FULLMASK, cand);
        int buf = it & 1;
        if (lane == 0) { swv[buf][w] = mx; swi[buf][w] = mi; }
        __syncthreads();
        unsigned v2 = swv[buf][lane];
        unsigned i2 = swi[buf][lane];
        unsigned mx2 = __reduce_max_sync(FULLMASK, v2);
        unsigned c2 = (v2 == mx2) ? i2 : 0xffffffffu;
        far = (int)__reduce_min_sync(FULLMASK, c2);
    }
}

// ------------- prep: ||x||^2 + gather new_xyz -------------
__global__ void prep_kernel(const float* __restrict__ xyz, float* __restrict__ out, int write_xyz) {
    int i = blockIdx.x * 256 + threadIdx.x;
    if (i < B_ * N_) {
        float x = xyz[3*i], y = xyz[3*i+1], z = xyz[3*i+2];
        g_d2[i] = __fadd_rn(__fadd_rn(__fmul_rn(x,x), __fmul_rn(y,y)), __fmul_rn(z,z));
    }
    if (i < B_ * S_) {
        int b = i >> 10, n = g_fps[i];
        const float* p = xyz + ((size_t)b * N_ + n) * 3;
        float px = p[0], py = p[1], pz = p[2];
        g_newxyz[3*i] = px; g_newxyz[3*i+1] = py; g_newxyz[3*i+2] = pz;
        if (write_xyz) { out[3*i] = px; out[3*i+1] = py; out[3*i+2] = pz; }
    }
}

// ------------- KNN: warp per query, bitonic top-32, exact fp32 -------------
__global__ void __launch_bounds__(256) knn_kernel(const float* __restrict__ xyz) {
    extern __shared__ float sh[];
    float* sx = sh; float* sy = sh + N_; float* sz = sh + 2*N_; float* sd = sh + 3*N_;
    int t = threadIdx.x;
    int b = blockIdx.x >> 7;
    int s0 = (blockIdx.x & 127) * 8;
    const float* X = xyz + (size_t)b * N_ * 3;
    for (int i = t; i < N_; i += 256) {
        sx[i] = X[3*i]; sy[i] = X[3*i+1]; sz[i] = X[3*i+2];
        sd[i] = g_d2[b * N_ + i];
    }
    __syncthreads();
    int w = t >> 5, lane = t & 31;
    int q = b * S_ + s0 + w;
    float qx = g_newxyz[3*q], qy = g_newxyz[3*q+1], qz = g_newxyz[3*q+2];
    float q2 = __fadd_rn(__fadd_rn(__fmul_rn(qx,qx), __fmul_rn(qy,qy)), __fmul_rn(qz,qz));
    float key = 3.0e38f; int kid = 0; float curmax = 3.0e38f;
    for (int c = 0; c < N_ / 32; c++) {
        int p = c * 32 + lane;
        float dot = __fadd_rn(__fadd_rn(__fmul_rn(qx, sx[p]),
                                        __fmul_rn(qy, sy[p])),
                              __fmul_rn(qz, sz[p]));
        float d = __fsub_rn(__fadd_rn(q2, sd[p]), __fmul_rn(2.0f, dot));
        if (!__ballot_sync(FULLMASK, d < curmax)) continue;
        float nk = d; int ni = p;
        bitonic_sort_asc(nk, ni, lane);
        float rk = __shfl_sync(FULLMASK, nk, 31 - lane);
        int   ri = __shfl_sync(FULLMASK, ni, 31 - lane);
        if (rk < key) { key = rk; kid = ri; }
        bitonic_merge_asc(key, kid, lane);
        curmax = __shfl_sync(FULLMASK, key, 31);
    }
    g_nn[q * K_ + lane] = kid;
}

// ================= shared GEMM epilogue helper (layers 0/1) =================
// tile: block = 256 rows x 64 cols, thread = 16 rows x 8 cols (row-pair packed)

// ------------- layer 0: gather + GEMM 67->64 -------------
__global__ void __launch_bounds__(128, 1) layer0_kernel(const float* __restrict__ xyz,
                                                        const float* __restrict__ points,
                                                        const float* __restrict__ w,
                                                        const float* __restrict__ bias) {
    extern __shared__ float sh[];
    float* XsT = sh;                   // [68][256]
    float* Ws  = XsT + 68 * 256;       // [67][64]
    float* Red = Ws + 67 * 64;         // 2 x [16][65]
    int t = threadIdx.x;
    for (int idx = t; idx < 67 * 64; idx += 128) {
        int cc = idx >> 6, o = idx & 63;
        int c = (cc < 64) ? (cc + 3) : (cc - 64);
        Ws[idx] = w[o * 67 + c];
    }
    #pragma unroll
    for (int rr = 0; rr < 2; rr++) {
        int r = t + rr * 128;
        int gr = blockIdx.x * 256 + r;
        int q = gr >> 5, b = gr >> 15;
        int n = g_nn[gr];
        const float4* prow = (const float4*)(points + ((size_t)b * N_ + n) * 64);
        #pragma unroll 4
        for (int ch = 0; ch < 16; ch++) {
            float4 v = prow[ch];
            XsT[(ch*4+0)*256 + r] = v.x;
            XsT[(ch*4+1)*256 + r] = v.y;
            XsT[(ch*4+2)*256 + r] = v.z;
            XsT[(ch*4+3)*256 + r] = v.w;
        }
        const float* pp = xyz + ((size_t)b * N_ + n) * 3;
        XsT[64*256 + r] = __fadd_rn(pp[0], -g_newxyz[3*q]);
        XsT[65*256 + r] = __fadd_rn(pp[1], -g_newxyz[3*q+1]);
        XsT[66*256 + r] = __fadd_rn(pp[2], -g_newxyz[3*q+2]);
    }
    __syncthreads();
    int rg = t >> 3, cg = t & 7;       // rows rg*16..+15, cols cg*8..+7
    ull acc[8][8];                     // [row-pair][col]; lanes = rows (2p, 2p+1)
    #pragma unroll
    for (int i = 0; i < 8; i++) {
        float bb = bias[cg*8+i];
        ull bp = pack2(bb, bb);
        #pragma unroll
        for (int p = 0; p < 8; p++) acc[p][i] = bp;
    }
    for (int c = 0; c < 67; c++) {
        const float4* ap = (const float4*)(XsT + c*256 + rg*16);
        float4 a0 = ap[0], a1 = ap[1], a2 = ap[2], a3 = ap[3];
        ull apair[8] = {pack2(a0.x,a0.y), pack2(a0.z,a0.w),
                        pack2(a1.x,a1.y), pack2(a1.z,a1.w),
                        pack2(a2.x,a2.y), pack2(a2.z,a2.w),
                        pack2(a3.x,a3.y), pack2(a3.z,a3.w)};
        const float4* wp = (const float4*)(Ws + c*64 + cg*8);
        float4 w0 = wp[0], w1 = wp[1];
        float wf[8] = {w0.x,w0.y,w0.z,w0.w,w1.x,w1.y,w1.z,w1.w};
        #pragma unroll
        for (int i = 0; i < 8; i++) {
            ull wd = pack2(wf[i], wf[i]);
            #pragma unroll
            for (int p = 0; p < 8; p++) fma2(acc[p][i], apair[p], wd);
        }
    }
    float s1[8], s2[8];
    #pragma unroll
    for (int i = 0; i < 8; i++) { s1[i] = 0.f; s2[i] = 0.f; }
    #pragma unroll
    for (int p = 0; p < 8; p++) {
        float lo[8], hi[8];
        #pragma unroll
        for (int i = 0; i < 8; i++) { float2 v = unpack2(acc[p][i]); lo[i] = v.x; hi[i] = v.y; }
        size_t r0 = (size_t)blockIdx.x * 256 + rg*16 + 2*p;
        float4* d0 = (float4*)(g_y0 + r0 * 64 + cg*8);
        d0[0] = make_float4(lo[0],lo[1],lo[2],lo[3]);
        d0[1] = make_float4(lo[4],lo[5],lo[6],lo[7]);
        float4* d1 = (float4*)(g_y0 + (r0+1) * 64 + cg*8);
        d1[0] = make_float4(hi[0],hi[1],hi[2],hi[3]);
        d1[1] = make_float4(hi[4],hi[5],hi[6],hi[7]);
        #pragma unroll
        for (int i = 0; i < 8; i++) { s1[i] += lo[i]+hi[i]; s2[i] += lo[i]*lo[i]+hi[i]*hi[i]; }
    }
    #pragma unroll
    for (int i = 0; i < 8; i++) {
        int col = cg*8 + i;
        Red[rg*65 + col]        = s1[i];
        Red[1040 + rg*65 + col] = s2[i];
    }
    __syncthreads();
    if (t < 64) {
        float s = 0.f;
        #pragma unroll 4
        for (int j = 0; j < 16; j++) s += Red[j*65 + t];
        g_part0[blockIdx.x*128 + t] = s;
    } else {
        int col = t - 64; float s = 0.f;
        #pragma unroll 4
        for (int j = 0; j < 16; j++) s += Red[1040 + j*65 + col];
        g_part0[blockIdx.x*128 + 64 + col] = s;
    }
}

// ------------- layer 1: BN0+ReLU fused gather, GEMM 64->64 -------------
__global__ void __launch_bounds__(128, 1) layer1_kernel(const float* __restrict__ w,
                                                        const float* __restrict__ bias) {
    extern __shared__ float sh[];
    float* XsT = sh;                   // [64][256]
    float* Ws  = XsT + 64 * 256;       // [64][64]
    float* Red = Ws + 64 * 64;         // 2 x [16][65]
    __shared__ float sS[64], sH[64];
    int t = threadIdx.x;
    if (t < 64) { sS[t] = g_scale0[t]; sH[t] = g_shift0[t]; }
    for (int idx = t; idx < 64 * 64; idx += 128) {
        int c = idx >> 6, o = idx & 63;
        Ws[idx] = w[o * 64 + c];
    }
    __syncthreads();
    #pragma unroll
    for (int rr = 0; rr < 2; rr++) {
        int r = t + rr * 128;
        size_t gr = (size_t)blockIdx.x * 256 + r;
        const float4* src = (const float4*)(g_y0 + gr * 64);
        #pragma unroll 4
        for (int ch = 0; ch < 16; ch++) {
            float4 v = src[ch]; int c0 = ch * 4;
            XsT[(c0+0)*256 + r] = fmaxf(0.f, fmaf(v.x, sS[c0],   sH[c0]));
            XsT[(c0+1)*256 + r] = fmaxf(0.f, fmaf(v.y, sS[c0+1], sH[c0+1]));
            XsT[(c0+2)*256 + r] = fmaxf(0.f, fmaf(v.z, sS[c0+2], sH[c0+2]));
            XsT[(c0+3)*256 + r] = fmaxf(0.f, fmaf(v.w, sS[c0+3], sH[c0+3]));
        }
    }
    __syncthreads();
    int rg = t >> 3, cg = t & 7;
    ull acc[8][8];
    #pragma unroll
    for (int i = 0; i < 8; i++) {
        float bb = bias[cg*8+i];
        ull bp = pack2(bb, bb);
        #pragma unroll
        for (int p = 0; p < 8; p++) acc[p][i] = bp;
    }
    for (int c = 0; c < 64; c++) {
        const float4* ap = (const float4*)(XsT + c*256 + rg*16);
        float4 a0 = ap[0], a1 = ap[1], a2 = ap[2], a3 = ap[3];
        ull apair[8] = {pack2(a0.x,a0.y), pack2(a0.z,a0.w),
                        pack2(a1.x,a1.y), pack2(a1.z,a1.w),
                        pack2(a2.x,a2.y), pack2(a2.z,a2.w),
                        pack2(a3.x,a3.y), pack2(a3.z,a3.w)};
        const float4* wp = (const float4*)(Ws + c*64 + cg*8);
        float4 w0 = wp[0], w1 = wp[1];
        float wf[8] = {w0.x,w0.y,w0.z,w0.w,w1.x,w1.y,w1.z,w1.w};
        #pragma unroll
        for (int i = 0; i < 8; i++) {
            ull wd = pack2(wf[i], wf[i]);
            #pragma unroll
            for (int p = 0; p < 8; p++) fma2(acc[p][i], apair[p], wd);
        }
    }
    float s1[8], s2[8];
    #pragma unroll
    for (int i = 0; i < 8; i++) { s1[i] = 0.f; s2[i] = 0.f; }
    #pragma unroll
    for (int p = 0; p < 8; p++) {
        float lo[8], hi[8];
        #pragma unroll
        for (int i = 0; i < 8; i++) { float2 v = unpack2(acc[p][i]); lo[i] = v.x; hi[i] = v.y; }
        size_t r0 = (size_t)blockIdx.x * 256 + rg*16 + 2*p;
        float4* d0 = (float4*)(g_y1 + r0 * 64 + cg*8);
        d0[0] = make_float4(lo[0],lo[1],lo[2],lo[3]);
        d0[1] = make_float4(lo[4],lo[5],lo[6],lo[7]);
        float4* d1 = (float4*)(g_y1 + (r0+1) * 64 + cg*8);
        d1[0] = make_float4(hi[0],hi[1],hi[2],hi[3]);
        d1[1] = make_float4(hi[4],hi[5],hi[6],hi[7]);
        #pragma unroll
        for (int i = 0; i < 8; i++) { s1[i] += lo[i]+hi[i]; s2[i] += lo[i]*lo[i]+hi[i]*hi[i]; }
    }
    #pragma unroll
    for (int i = 0; i < 8; i++) {
        int col = cg*8 + i;
        Red[rg*65 + col]        = s1[i];
        Red[1040 + rg*65 + col] = s2[i];
    }
    __syncthreads();
    if (t < 64) {
        float s = 0.f;
        #pragma unroll 4
        for (int j = 0; j < 16; j++) s += Red[j*65 + t];
        g_part1[blockIdx.x*128 + t] = s;
    } else {
        int col = t - 64; float s = 0.f;
        #pragma unroll 4
        for (int j = 0; j < 16; j++) s += Red[1040 + j*65 + col];
        g_part1[blockIdx.x*128 + 64 + col] = s;
    }
}

// ------------- layer 2 fused: BN1+ReLU gather, GEMM 64->128, max/min over K ----
__global__ void __launch_bounds__(256, 1) layer2_kernel(const float* __restrict__ w,
                                                        const float* __restrict__ bias) {
    extern __shared__ float sh[];
    float* XsT = sh;                   // [64][256]
    float* Ws  = XsT + 64 * 256;       // [64][128]
    float* Red = Ws + 64 * 128;        // 2 x [16][129]
    __shared__ float sS[64], sH[64];
    int t = threadIdx.x;
    if (t < 64) { sS[t] = g_scale1[t]; sH[t] = g_shift1[t]; }
    for (int idx = t; idx < 64 * 128; idx += 256) {
        int c = idx >> 7, o = idx & 127;
        Ws[idx] = w[o * 64 + c];
    }
    __syncthreads();
    {
        int r = t;
        size_t gr = (size_t)blockIdx.x * 256 + r;
        const float4* src = (const float4*)(g_y1 + gr * 64);
        #pragma unroll 4
        for (int ch = 0; ch < 16; ch++) {
            float4 v = src[ch]; int c0 = ch * 4;
            XsT[(c0+0)*256 + r] = fmaxf(0.f, fmaf(v.x, sS[c0],   sH[c0]));
            XsT[(c0+1)*256 + r] = fmaxf(0.f, fmaf(v.y, sS[c0+1], sH[c0+1]));
            XsT[(c0+2)*256 + r] = fmaxf(0.f, fmaf(v.z, sS[c0+2], sH[c0+2]));
            XsT[(c0+3)*256 + r] = fmaxf(0.f, fmaf(v.w, sS[c0+3], sH[c0+3]));
        }
    }
    __syncthreads();
    int rg = t >> 4, cg = t & 15;      // rows rg*16..+15 (256), cols cg*8..+7 (128)
    ull acc[8][8];
    #pragma unroll
    for (int i = 0; i < 8; i++) {
        float bb = bias[cg*8+i];
        ull bp = pack2(bb, bb);
        #pragma unroll
        for (int p = 0; p < 8; p++) acc[p][i] = bp;
    }
    for (int c = 0; c < 64; c++) {
        const float4* ap = (const float4*)(XsT + c*256 + rg*16);
        float4 a0 = ap[0], a1 = ap[1], a2 = ap[2], a3 = ap[3];
        ull apair[8] = {pack2(a0.x,a0.y), pack2(a0.z,a0.w),
                        pack2(a1.x,a1.y), pack2(a1.z,a1.w),
                        pack2(a2.x,a2.y), pack2(a2.z,a2.w),
                        pack2(a3.x,a3.y), pack2(a3.z,a3.w)};
        const float4* wp = (const float4*)(Ws + c*128 + cg*8);
        float4 w0 = wp[0], w1 = wp[1];
        float wf[8] = {w0.x,w0.y,w0.z,w0.w,w1.x,w1.y,w1.z,w1.w};
        #pragma unroll
        for (int i = 0; i < 8; i++) {
            ull wd = pack2(wf[i], wf[i]);
            #pragma unroll
            for (int p = 0; p < 8; p++) fma2(acc[p][i], apair[p], wd);
        }
    }
    // stats + max/min over this thread's 16 rows (all within (b,s) group rg>>1)
    float s1[8], s2[8], mx[8], mn[8];
    #pragma unroll
    for (int i = 0; i < 8; i++) { s1[i]=0.f; s2[i]=0.f; mx[i]=-3.4e38f; mn[i]=3.4e38f; }
    #pragma unroll
    for (int p = 0; p < 8; p++) {
        #pragma unroll
        for (int i = 0; i < 8; i++) {
            float2 v = unpack2(acc[p][i]);
            s1[i] += v.x + v.y;
            s2[i] += v.x*v.x + v.y*v.y;
            mx[i] = fmaxf(mx[i], fmaxf(v.x, v.y));
            mn[i] = fminf(mn[i], fminf(v.x, v.y));
        }
    }
    #pragma unroll
    for (int i = 0; i < 8; i++) {
        int col = cg*8 + i;
        Red[rg*129 + col]        = s1[i];
        Red[2064 + rg*129 + col] = s2[i];
    }
    __syncthreads();
    if (t < 128) {
        float s = 0.f;
        #pragma unroll 4
        for (int j = 0; j < 16; j++) s += Red[j*129 + t];
        g_part2[blockIdx.x*256 + t] = s;
    } else {
        int col = t - 128; float s = 0.f;
        #pragma unroll 4
        for (int j = 0; j < 16; j++) s += Red[2064 + j*129 + col];
        g_part2[blockIdx.x*256 + 128 + col] = s;
    }
    __syncthreads();
    #pragma unroll
    for (int i = 0; i < 8; i++) {
        int col = cg*8 + i;
        Red[rg*129 + col]        = mx[i];
        Red[2064 + rg*129 + col] = mn[i];
    }
    __syncthreads();
    {
        // 8 (b,s) groups of 32 rows: group g combines Red rows 2g, 2g+1
        int col = t & 127, which = t >> 7;   // 0=max, 1=min
        #pragma unroll
        for (int g = 0; g < 8; g++) {
            size_t bs = (size_t)blockIdx.x * 8 + g;
            if (which == 0) {
                float m = fmaxf(Red[(2*g)*129 + col], Red[(2*g+1)*129 + col]);
                g_pmax[bs*128 + col] = m;
            } else {
                float n = fminf(Red[2064 + (2*g)*129 + col], Red[2064 + (2*g+1)*129 + col]);
                g_pmin[bs*128 + col] = n;
            }
        }
    }
}

// ------------- BN stats -------------
__global__ void __launch_bounds__(256) stats_kernel(int layer, int nblk, int C,
                             const float* __restrict__ gamma, const float* __restrict__ beta) {
    int c = blockIdx.x;
    int t = threadIdx.x;
    const float* part = (layer == 0) ? g_part0 : (layer == 1) ? g_part1 : g_part2;
    float s1 = 0.f, s2 = 0.f;
    for (int bk = t; bk < nblk; bk += 256) {
        s1 += part[(size_t)bk*2*C + c];
        s2 += part[(size_t)bk*2*C + C + c];
    }
    __shared__ float r1[256], r2[256];
    r1[t] = s1; r2[t] = s2;
    __syncthreads();
    for (int off = 128; off >= 1; off >>= 1) {
        if (t < off) { r1[t] += r1[t+off]; r2[t] += r2[t+off]; }
        __syncthreads();
    }
    if (t == 0) {
        const float n = 524288.f;
        float mean = r1[0] / n;
        float var = r2[0] / n - mean * mean;
        float sc = gamma[c] * rsqrtf(var + EPSF);
        float sf = beta[c] - mean * sc;
        if (layer == 0)      { g_scale0[c] = sc; g_shift0[c] = sf; }
        else if (layer == 1) { g_scale1[c] = sc; g_shift1[c] = sf; }
        else                 { g_scale2[c] = sc; g_shift2[c] = sf; }
    }
}

// ------------- pool epilogue -------------
__global__ void pool2_kernel(float* __restrict__ out, int pts_off) {
    int bs = blockIdx.x;
    int c = threadIdx.x;
    float sc = g_scale2[c], sf = g_shift2[c];
    float v = (sc >= 0.f) ? g_pmax[(size_t)bs*128 + c] : g_pmin[(size_t)bs*128 + c];
    float m = fmaxf(fmaf(v, sc, sf), 0.f);
    out[pts_off + (bs >> 10) * (128 * 1024) + c * 1024 + (bs & 1023)] = m;
}

extern "C" void kernel_launch(void* const* d_in, const int* in_sizes, int n_in,
                              void* d_out, int out_size) {
    const float* xyz    = (const float*)d_in[0];
    const float* points = (const float*)d_in[1];
    const float* w0 = (const float*)d_in[2];  const float* b0  = (const float*)d_in[3];
    const float* g0 = (const float*)d_in[4];  const float* be0 = (const float*)d_in[5];
    const float* w1 = (const float*)d_in[6];  const float* b1  = (const float*)d_in[7];
    const float* g1 = (const float*)d_in[8];  const float* be1 = (const float*)d_in[9];
    const float* w2 = (const float*)d_in[10]; const float* b2  = (const float*)d_in[11];
    const float* g2 = (const float*)d_in[12]; const float* be2 = (const float*)d_in[13];
    float* out = (float*)d_out;

    int npts = B_ * 128 * S_;
    int pts_off = out_size - npts;
    if (pts_off < 0) pts_off = 0;

    cudaFuncSetAttribute(fps_kernel,    cudaFuncAttributeMaxDynamicSharedMemorySize, FPS_SMEM);
    cudaFuncSetAttribute(knn_kernel,    cudaFuncAttributeMaxDynamicSharedMemorySize, KNN_SMEM);
    cudaFuncSetAttribute(layer0_kernel, cudaFuncAttributeMaxDynamicSharedMemorySize, L0_SMEM);
    cudaFuncSetAttribute(layer1_kernel, cudaFuncAttributeMaxDynamicSharedMemorySize, L1_SMEM);
    cudaFuncSetAttribute(layer2_kernel, cudaFuncAttributeMaxDynamicSharedMemorySize, L2_SMEM);

    fps_kernel<<<B_, 1024, FPS_SMEM>>>(xyz);
    prep_kernel<<<(B_ * N_ + 255) / 256, 256>>>(xyz, out, pts_off > 0 ? 1 : 0);
    knn_kernel<<<B_ * 128, 256, KNN_SMEM>>>(xyz);
    layer0_kernel<<<2048, 128, L0_SMEM>>>(xyz, points, w0, b0);
    stats_kernel<<<64, 256>>>(0, 2048, 64, g0, be0);
    layer1_kernel<<<2048, 128, L1_SMEM>>>(w1, b1);
    stats_kernel<<<64, 256>>>(1, 2048, 64, g1, be1);
    layer2_kernel<<<2048, 256, L2_SMEM>>>(w2, b2);
    stats_kernel<<<128, 256>>>(2, 2048, 128, g2, be2);
    pool2_kernel<<<B_ * S_, 128>>>(out, pts_off);
}